// round 11
// baseline (speedup 1.0000x reference)
#include <cuda_runtime.h>
#include <cuda_fp16.h>
#include <cstdint>
#include <math.h>

#define DIMC 1024
#define NH   16
#define HD   64
#define NPOS 1024
#define BATCHN 16
#define KPROJ 512

// ---------------- scratch ----------------
__device__ __half g_wf16[2 * DIMC * KPROJ];                 // W rounded fp16
__device__ __half g_xh[BATCHN * DIMC * NPOS];               // x fp16, native [b][c][p]
__device__ __half g_qh[BATCHN * DIMC * NPOS];               // unroped q fp16 [b][o][p]
__device__ __half g_kh[BATCHN * DIMC * NPOS];               // unroped k
__device__ float g_km[BATCHN * DIMC];
__device__ float g_kv[BATCHN * NH * HD * HD];               // [bh][e][d] fp32 accum
__device__ float g_cos[(DIMC / 2) * NPOS];                  // [j][p]
__device__ float g_sin[(DIMC / 2) * NPOS];

// ---------------- helpers ----------------
__device__ __forceinline__ void mmaf16(float c[4], const uint32_t a[4], const uint32_t b[2]) {
    asm volatile(
        "mma.sync.aligned.m16n8k16.row.col.f32.f16.f16.f32 "
        "{%0,%1,%2,%3}, {%4,%5,%6,%7}, {%8,%9}, {%0,%1,%2,%3};"
        : "+f"(c[0]), "+f"(c[1]), "+f"(c[2]), "+f"(c[3])
        : "r"(a[0]), "r"(a[1]), "r"(a[2]), "r"(a[3]), "r"(b[0]), "r"(b[1]));
}

__device__ __forceinline__ void splith(float v, __half& hi, __half& lo) {
    hi = __float2half_rn(v);
    lo = __float2half_rn(v - __half2float(hi));
}

__device__ __forceinline__ uint32_t packh(__half a, __half b) {
    return (uint32_t)__half_as_ushort(a) | ((uint32_t)__half_as_ushort(b) << 16);
}

__device__ __forceinline__ float elu1(float v) { return v > 0.f ? v + 1.f : expf(v); }

__device__ __forceinline__ uint32_t cvta_sm(const void* p) {
    return (uint32_t)__cvta_generic_to_shared(p);
}

__device__ __forceinline__ void cp16(uint32_t saddr, const void* g) {
    asm volatile("cp.async.cg.shared.global [%0], [%1], 16;" :: "r"(saddr), "l"(g));
}

__device__ __forceinline__ void ldsm4(uint32_t r[4], uint32_t addr) {
    asm volatile("ldmatrix.sync.aligned.m8n8.x4.shared.b16 {%0,%1,%2,%3}, [%4];"
                 : "=r"(r[0]), "=r"(r[1]), "=r"(r[2]), "=r"(r[3]) : "r"(addr));
}

__device__ __forceinline__ void ldsm4t(uint32_t r[4], uint32_t addr) {
    asm volatile("ldmatrix.sync.aligned.m8n8.x4.trans.shared.b16 {%0,%1,%2,%3}, [%4];"
                 : "=r"(r[0]), "=r"(r[1]), "=r"(r[2]), "=r"(r[3]) : "r"(addr));
}

// ---------------- prep kernels ----------------
__global__ void prep_misc_kernel() {
    int idx = blockIdx.x * blockDim.x + threadIdx.x;
    if (idx < (DIMC / 2) * NPOS) {
        int j = idx >> 10, p = idx & (NPOS - 1);
        int jj = (j < 256) ? j : j - 256;
        float pos = (float)((j < 256) ? (p >> 5) : (p & 31));
        float theta = expf(-(float)jj * (9.210340371976184f / 256.f));
        float ang = pos * theta;
        float s, c;
        sincosf(ang, &s, &c);
        g_cos[idx] = c;
        g_sin[idx] = s;
    }
    if (idx < BATCHN * NH * HD * HD) g_kv[idx] = 0.f;
    if (idx < BATCHN * DIMC) g_km[idx] = 0.f;
}

__global__ void prep_w_kernel(const float* __restrict__ qk_w) {
    int idx = blockIdx.x * blockDim.x + threadIdx.x;
    if (idx < 2 * DIMC * KPROJ) g_wf16[idx] = __float2half_rn(qk_w[idx]);
}

// x fp32 -> fp16, layout preserved
__global__ __launch_bounds__(256) void xhalf_kernel(const float* __restrict__ x) {
    size_t i = (size_t)blockIdx.x * 256 + threadIdx.x;   // over 16M/8
    const float4* X4 = (const float4*)x;
    float4 a = X4[2 * i], b = X4[2 * i + 1];
    uint4 o;
    o.x = packh(__float2half_rn(a.x), __float2half_rn(a.y));
    o.y = packh(__float2half_rn(a.z), __float2half_rn(a.w));
    o.z = packh(__float2half_rn(b.x), __float2half_rn(b.y));
    o.w = packh(__float2half_rn(b.z), __float2half_rn(b.w));
    ((uint4*)g_xh)[i] = o;
}

// ---------------- projection GEMM: fp16, 4-stage pipeline, B from native [c][p] ----------------
#define PSTR 40
#define PB_STR 136
#define APLANE (128 * PSTR)                  // 5120
#define BPLANE (32 * PB_STR)                 // 4352
#define STG (APLANE + BPLANE)                // 9472
#define NSTAGE 4
#define PROJ_SMEM (NSTAGE * STG * 2)         // 75776 bytes

__global__ __launch_bounds__(256, 3) void proj_kernel(const float* __restrict__ qk_b) {
    extern __shared__ __align__(16) __half sm[];

    int tid = threadIdx.x;
    int lane = tid & 31, wid = tid >> 5;
    int wm = wid >> 2, wn = wid & 3;
    int g4 = lane >> 2, tg = lane & 3;
    int arow = (lane & 7) + ((lane >> 3) & 1) * 8;
    int acol = (lane >> 4) * 8;

    int pt = blockIdx.x, ot = blockIdx.y;
    int b = blockIdx.z >> 1, grp = blockIdx.z & 1;
    const __half* W = g_wf16 + (size_t)grp * DIMC * KPROJ;
    const __half* Xc = g_xh + ((size_t)b * DIMC + grp * KPROJ) * NPOS;
    int o0 = ot * 128, p0 = pt * 128;

    float c[4][4][4];
#pragma unroll
    for (int i = 0; i < 4; i++)
#pragma unroll
        for (int j = 0; j < 4; j++)
#pragma unroll
            for (int k = 0; k < 4; k++) c[i][j][k] = 0.f;

    int so = tid >> 2;
    int scs = (tid & 3) * 8;
    const __half* Wg = W + (size_t)(o0 + so) * KPROJ + scs;
    uint32_t smem_base = cvta_sm(sm);

    auto issue = [&](int kt) {
        uint32_t st = smem_base + ((kt & (NSTAGE - 1)) * STG) * 2;
        int c0 = kt * 32;
        // A: W rows o (128 x 32)
        cp16(st + (so * PSTR + scs) * 2, Wg + c0);
        cp16(st + ((so + 64) * PSTR + scs) * 2, Wg + (size_t)64 * KPROJ + c0);
        // B: X rows c (32 x 128), native layout
#pragma unroll
        for (int i = tid; i < 512; i += 256) {
            int row = i >> 4, ch = (i & 15) * 8;
            cp16(st + (APLANE + row * PB_STR + ch) * 2,
                 Xc + (size_t)(c0 + row) * NPOS + p0 + ch);
        }
    };

    issue(0);
    asm volatile("cp.async.commit_group;");
    issue(1);
    asm volatile("cp.async.commit_group;");
    issue(2);
    asm volatile("cp.async.commit_group;");

    for (int kt = 0; kt < 16; kt++) {
        if (kt < 14)       asm volatile("cp.async.wait_group 2;");
        else if (kt == 14) asm volatile("cp.async.wait_group 1;");
        else               asm volatile("cp.async.wait_group 0;");
        __syncthreads();

        uint32_t stA = smem_base + ((kt & (NSTAGE - 1)) * STG) * 2;
        uint32_t stB = stA + APLANE * 2;

#pragma unroll
        for (int ks = 0; ks < 2; ks++) {
            int kk = ks * 16;
            uint32_t a4[4][4];
#pragma unroll
            for (int mi = 0; mi < 4; mi++)
                ldsm4(a4[mi], stA + ((wm * 64 + mi * 16 + arow) * PSTR + kk + acol) * 2);
            uint32_t bf[4][2];
#pragma unroll
            for (int nip = 0; nip < 2; nip++) {
                uint32_t r[4];
                ldsm4t(r, stB + ((kk + arow) * PB_STR + wn * 32 + nip * 16 + acol) * 2);
                bf[2 * nip][0] = r[0]; bf[2 * nip][1] = r[1];
                bf[2 * nip + 1][0] = r[2]; bf[2 * nip + 1][1] = r[3];
            }
#pragma unroll
            for (int mi = 0; mi < 4; mi++)
#pragma unroll
                for (int ni = 0; ni < 4; ni++)
                    mmaf16(c[mi][ni], a4[mi], bf[ni]);
        }

        if (kt + 3 < 16) {
            issue(kt + 3);
            asm volatile("cp.async.commit_group;");
        }
    }

    // epilogue: bias + elu + 1, fp16 store (unroped), km atomics for k-group
    __half* dst = (grp ? g_kh : g_qh) + (size_t)b * DIMC * NPOS;
#pragma unroll
    for (int mi = 0; mi < 4; mi++) {
        int r0 = o0 + wm * 64 + mi * 16 + g4;
        int r1 = r0 + 8;
        float bias0 = __ldg(&qk_b[grp * DIMC + r0]);
        float bias1 = __ldg(&qk_b[grp * DIMC + r1]);
        float rs0 = 0.f, rs1 = 0.f;
#pragma unroll
        for (int ni = 0; ni < 4; ni++) {
            int p = p0 + wn * 32 + ni * 8 + tg * 2;
            float v00 = elu1(c[mi][ni][0] + bias0);
            float v01 = elu1(c[mi][ni][1] + bias0);
            float v10 = elu1(c[mi][ni][2] + bias1);
            float v11 = elu1(c[mi][ni][3] + bias1);
            *(uint32_t*)&dst[(size_t)r0 * NPOS + p] = packh(__float2half_rn(v00), __float2half_rn(v01));
            *(uint32_t*)&dst[(size_t)r1 * NPOS + p] = packh(__float2half_rn(v10), __float2half_rn(v11));
            rs0 += v00 + v01;
            rs1 += v10 + v11;
        }
        if (grp) {
            rs0 += __shfl_xor_sync(0xffffffffu, rs0, 1);
            rs0 += __shfl_xor_sync(0xffffffffu, rs0, 2);
            rs1 += __shfl_xor_sync(0xffffffffu, rs1, 1);
            rs1 += __shfl_xor_sync(0xffffffffu, rs1, 2);
            if (tg == 0) {
                atomicAdd(&g_km[b * DIMC + r0], rs0 * (1.f / NPOS));
                atomicAdd(&g_km[b * DIMC + r1], rs1 * (1.f / NPOS));
            }
        }
    }
}

// ---------------- kv kernel (n-split x4): rope k during staging, 2 MMAs ----------------
#define KV_STR 72

__global__ __launch_bounds__(256) void kv_kernel(const float* __restrict__ x) {
    __shared__ __align__(16) __half sa[64 * KV_STR];      // rope(k) [d][n]
    __shared__ __align__(16) __half sb[2][64 * KV_STR];   // v hi/lo [e][n]

    int tid = threadIdx.x;
    int lane = tid & 31, wid = tid >> 5;
    int wm = wid >> 2, wn = wid & 3;
    int g4 = lane >> 2, tg = lane & 3;
    int bh = blockIdx.x, chunk = blockIdx.y;
    int b = bh >> 4, h = bh & 15;
    size_t base = ((size_t)b * DIMC + h * HD) * NPOS;
    const __half* K = g_kh + base;
    const float* V = x + base;

    int kd2 = tid >> 3, kng = (tid & 7) * 8;
    int ve = tid >> 2, vng = (tid & 3) * 16;

    float c[2][2][4];
#pragma unroll
    for (int i = 0; i < 2; i++)
#pragma unroll
        for (int j = 0; j < 2; j++)
#pragma unroll
            for (int k = 0; k < 4; k++) c[i][j][k] = 0.f;

    for (int sub = 0; sub < 4; sub++) {
        int n0 = chunk * 256 + sub * 64;
        // stage rope(k): 8 n per thread
        {
            int r0 = 2 * kd2, r1 = r0 + 1;
            size_t o0 = (size_t)r0 * NPOS + n0 + kng;
            size_t o1 = o0 + NPOS;
            uint4 kh0 = *(const uint4*)&K[o0];
            uint4 kh1 = *(const uint4*)&K[o1];
            const __half* p0 = (const __half*)&kh0;
            const __half* p1 = (const __half*)&kh1;
            int j = h * 32 + kd2;
            const float* Cp = &g_cos[(size_t)j * NPOS + n0 + kng];
            const float* Sp = &g_sin[(size_t)j * NPOS + n0 + kng];
            float4 cA = *(const float4*)Cp, cB = *(const float4*)(Cp + 4);
            float4 sA = *(const float4*)Sp, sB = *(const float4*)(Sp + 4);
            float csv[8] = {cA.x, cA.y, cA.z, cA.w, cB.x, cB.y, cB.z, cB.w};
            float snv[8] = {sA.x, sA.y, sA.z, sA.w, sB.x, sB.y, sB.z, sB.w};
            __half oh0[8], oh1[8];
#pragma unroll
            for (int t = 0; t < 8; t++) {
                float k0 = __half2float(p0[t]);
                float k1 = __half2float(p1[t]);
                oh0[t] = __float2half_rn(csv[t] * k0 - snv[t] * k1);
                oh1[t] = __float2half_rn(snv[t] * k0 + csv[t] * k1);
            }
            *(uint4*)&sa[r0 * KV_STR + kng] = *(uint4*)oh0;
            *(uint4*)&sa[r1 * KV_STR + kng] = *(uint4*)oh1;
        }
        // stage v hi/lo: 16 n per thread
        {
            const float* Vp = &V[(size_t)ve * NPOS + n0 + vng];
            __half vh[16], vl[16];
#pragma unroll
            for (int t4 = 0; t4 < 4; t4++) {
                float4 v = *(const float4*)(Vp + t4 * 4);
                splith(v.x, vh[t4 * 4 + 0], vl[t4 * 4 + 0]);
                splith(v.y, vh[t4 * 4 + 1], vl[t4 * 4 + 1]);
                splith(v.z, vh[t4 * 4 + 2], vl[t4 * 4 + 2]);
                splith(v.w, vh[t4 * 4 + 3], vl[t4 * 4 + 3]);
            }
            *(uint4*)&sb[0][ve * KV_STR + vng] = *(uint4*)vh;
            *(uint4*)&sb[0][ve * KV_STR + vng + 8] = *(uint4*)(vh + 8);
            *(uint4*)&sb[1][ve * KV_STR + vng] = *(uint4*)vl;
            *(uint4*)&sb[1][ve * KV_STR + vng + 8] = *(uint4*)(vl + 8);
        }
        __syncthreads();

#pragma unroll
        for (int ks = 0; ks < 4; ks++) {
            int kk = ks * 16;
            int col = kk + tg * 2;
            uint32_t ah[2][4];
#pragma unroll
            for (int mi = 0; mi < 2; mi++) {
                int d = wm * 32 + mi * 16 + g4;
                ah[mi][0] = *(uint32_t*)&sa[d * KV_STR + col];
                ah[mi][1] = *(uint32_t*)&sa[(d + 8) * KV_STR + col];
                ah[mi][2] = *(uint32_t*)&sa[d * KV_STR + col + 8];
                ah[mi][3] = *(uint32_t*)&sa[(d + 8) * KV_STR + col + 8];
            }
            uint32_t bh2[2][2], bl2[2][2];
#pragma unroll
            for (int ni = 0; ni < 2; ni++) {
                int e = wn * 16 + ni * 8 + g4;
                bh2[ni][0] = *(uint32_t*)&sb[0][e * KV_STR + col];
                bh2[ni][1] = *(uint32_t*)&sb[0][e * KV_STR + col + 8];
                bl2[ni][0] = *(uint32_t*)&sb[1][e * KV_STR + col];
                bl2[ni][1] = *(uint32_t*)&sb[1][e * KV_STR + col + 8];
            }
#pragma unroll
            for (int mi = 0; mi < 2; mi++)
#pragma unroll
                for (int ni = 0; ni < 2; ni++) {
                    mmaf16(c[mi][ni], ah[mi], bh2[ni]);
                    mmaf16(c[mi][ni], ah[mi], bl2[ni]);
                }
        }
        __syncthreads();
    }

    float* KV = g_kv + (size_t)bh * HD * HD;
#pragma unroll
    for (int mi = 0; mi < 2; mi++) {
#pragma unroll
        for (int ni = 0; ni < 2; ni++) {
            int d0 = wm * 32 + mi * 16 + g4, d1 = d0 + 8;
            int e0 = wn * 16 + ni * 8 + tg * 2, e1 = e0 + 1;
            atomicAdd(&KV[e0 * HD + d0], c[mi][ni][0] * (1.f / NPOS));
            atomicAdd(&KV[e1 * HD + d0], c[mi][ni][1] * (1.f / NPOS));
            atomicAdd(&KV[e0 * HD + d1], c[mi][ni][2] * (1.f / NPOS));
            atomicAdd(&KV[e1 * HD + d1], c[mi][ni][3] * (1.f / NPOS));
        }
    }
}

// ---------------- out kernel: 512 threads, attn + fused lepe, rope q + z in staging ----------------
#define OA_STR 66
#define OB_STR 72
#define OSMEM_BYTES ((128 * OA_STR + 2 * 64 * OB_STR) * 2 + (128 + 576 + 64 + 64 * 198) * 4)

__global__ __launch_bounds__(512, 2) void out_kernel(float* __restrict__ out,
                                                     const float* __restrict__ x,
                                                     const float* __restrict__ lepe_w,
                                                     const float* __restrict__ lepe_b) {
    extern __shared__ __align__(16) char sm_raw[];
    __half* sa = (__half*)sm_raw;              // roped q [n][d] 128 x OA_STR
    __half* skh = sa + 128 * OA_STR;
    __half* skl = skh + 64 * OB_STR;
    float* s_z = (float*)(skl + 64 * OB_STR);
    float* sw = s_z + 128;
    float* sbias = sw + 576;
    float* sx = sbias + 64;

    int tid = threadIdx.x;
    int lane = tid & 31, wid = tid >> 5;
    int wm = wid >> 2, wn = wid & 3;           // 4 n-groups x 4 e-groups
    int g4 = lane >> 2, tg = lane & 3;

    int nt = blockIdx.x, bh = blockIdx.y;
    int b = bh >> 4, h = bh & 15;
    int n0 = nt * 128;
    int y0 = nt * 4;
    size_t qbase = ((size_t)b * DIMC + h * HD) * NPOS;
    const __half* Q = g_qh + qbase;
    const float* km = g_km + b * DIMC + h * HD;

    if (tid < 128) s_z[tid] = 0.f;
    // stage kv hi/lo
    {
        const float* KV = g_kv + (size_t)bh * HD * HD;
        for (int i = tid; i < 4096; i += 512) {
            int e = i >> 6, d = i & 63;
            __half hi, lo;
            splith(KV[i], hi, lo);
            skh[e * OB_STR + d] = hi;
            skl[e * OB_STR + d] = lo;
        }
    }
    // stage lepe weights/bias
    for (int i = tid; i < 576; i += 512) sw[i] = __ldg(&lepe_w[h * 576 + i]);
    if (tid < 64) sbias[tid] = __ldg(&lepe_b[h * 64 + tid]);
    // stage x halo rows
    {
        const float* Xp = x + qbase;
#pragma unroll
        for (int rr = 0; rr < 6; rr++) {
            int yy = y0 - 1 + rr;
            bool valid = (yy >= 0) && (yy < 32);
            int i = tid;
            if (i < 512) {
                int e = i >> 3, q4 = (i & 7) * 4;
                float4 v = make_float4(0.f, 0.f, 0.f, 0.f);
                if (valid) v = *(const float4*)&Xp[(size_t)e * 1024 + yy * 32 + q4];
                float* d = &sx[e * 198 + rr * 33 + q4];
                d[0] = v.x; d[1] = v.y; d[2] = v.z; d[3] = v.w;
            }
        }
    }
    __syncthreads();

    // stage rope(q) + z partial: 4 thread-quarters cover d2 0..31 over 8 passes
    float zacc = 0.f;
    int nfix = tid & 127;
    int quarter = tid >> 7;
#pragma unroll 4
    for (int pass = 0; pass < 8; pass++) {
        int d2 = quarter + pass * 4;
        size_t i0 = (size_t)(2 * d2) * NPOS + n0 + nfix;
        size_t i1 = i0 + NPOS;
        float q0 = __half2float(Q[i0]);
        float q1 = __half2float(Q[i1]);
        float km0 = __ldg(&km[2 * d2]);
        float km1 = __ldg(&km[2 * d2 + 1]);
        zacc += q0 * km0 + q1 * km1;
        int j = h * 32 + d2;
        float cs = g_cos[(size_t)j * NPOS + n0 + nfix];
        float sn = g_sin[(size_t)j * NPOS + n0 + nfix];
        float r0 = cs * q0 - sn * q1;
        float r1 = sn * q0 + cs * q1;
        *(uint32_t*)&sa[nfix * OA_STR + 2 * d2] = packh(__float2half_rn(r0), __float2half_rn(r1));
    }
    atomicAdd(&s_z[nfix], zacc);
    __syncthreads();

    float c[2][2][4];
#pragma unroll
    for (int i = 0; i < 2; i++)
#pragma unroll
        for (int j = 0; j < 2; j++)
#pragma unroll
            for (int k = 0; k < 4; k++) c[i][j][k] = 0.f;

#pragma unroll
    for (int ks = 0; ks < 4; ks++) {
        int kk = ks * 16;
        int col = kk + tg * 2;
        uint32_t ah[2][4];
#pragma unroll
        for (int mi = 0; mi < 2; mi++) {
            int n = wm * 32 + mi * 16 + g4;
            ah[mi][0] = *(uint32_t*)&sa[n * OA_STR + col];
            ah[mi][1] = *(uint32_t*)&sa[(n + 8) * OA_STR + col];
            ah[mi][2] = *(uint32_t*)&sa[n * OA_STR + col + 8];
            ah[mi][3] = *(uint32_t*)&sa[(n + 8) * OA_STR + col + 8];
        }
        uint32_t bh2[2][2], bl2[2][2];
#pragma unroll
        for (int ni = 0; ni < 2; ni++) {
            int e = wn * 16 + ni * 8 + g4;
            bh2[ni][0] = *(uint32_t*)&skh[e * OB_STR + col];
            bh2[ni][1] = *(uint32_t*)&skh[e * OB_STR + col + 8];
            bl2[ni][0] = *(uint32_t*)&skl[e * OB_STR + col];
            bl2[ni][1] = *(uint32_t*)&skl[e * OB_STR + col + 8];
        }
#pragma unroll
        for (int mi = 0; mi < 2; mi++)
#pragma unroll
            for (int ni = 0; ni < 2; ni++) {
                mmaf16(c[mi][ni], ah[mi], bh2[ni]);
                mmaf16(c[mi][ni], ah[mi], bl2[ni]);
            }
    }

    // epilogue: z scale + fused lepe stencil
    float* O = out + qbase;
#pragma unroll
    for (int ni = 0; ni < 2; ni++) {
        int e0 = wn * 16 + ni * 8 + tg * 2;
        int e1 = e0 + 1;
        float b0 = sbias[e0], b1 = sbias[e1];

        auto lepe_at = [&](int e, float bs, int nr) -> float {
            int yloc = nr >> 5, xx = nr & 31;
            const float* base = &sx[e * 198 + yloc * 33];
            const float* wv = &sw[e * 9];
            float acc = bs;
#pragma unroll
            for (int i = 0; i < 3; i++) {
                const float* rw = base + i * 33;
                acc += wv[i * 3 + 1] * rw[xx];
                if (xx > 0)  acc += wv[i * 3 + 0] * rw[xx - 1];
                if (xx < 31) acc += wv[i * 3 + 2] * rw[xx + 1];
            }
            return acc;
        };

#pragma unroll
        for (int mi = 0; mi < 2; mi++) {
            int nr0 = wm * 32 + mi * 16 + g4;
            int nr1 = nr0 + 8;
            float z0 = 1.f / (s_z[nr0] + 1e-6f);
            float z1 = 1.f / (s_z[nr1] + 1e-6f);
            size_t i00 = (size_t)e0 * NPOS + n0 + nr0;
            size_t i01 = (size_t)e1 * NPOS + n0 + nr0;
            size_t i10 = (size_t)e0 * NPOS + n0 + nr1;
            size_t i11 = (size_t)e1 * NPOS + n0 + nr1;
            O[i00] = c[mi][ni][0] * z0 + lepe_at(e0, b0, nr0);
            O[i01] = c[mi][ni][1] * z0 + lepe_at(e1, b1, nr0);
            O[i10] = c[mi][ni][2] * z1 + lepe_at(e0, b0, nr1);
            O[i11] = c[mi][ni][3] * z1 + lepe_at(e1, b1, nr1);
        }
    }
}

// ---------------- launch ----------------
extern "C" void kernel_launch(void* const* d_in, const int* in_sizes, int n_in,
                              void* d_out, int out_size) {
    const float* x      = (const float*)d_in[0];
    const float* qk_w   = (const float*)d_in[1];
    const float* qk_b   = (const float*)d_in[2];
    const float* lepe_w = (const float*)d_in[3];
    const float* lepe_b = (const float*)d_in[4];
    float* out = (float*)d_out;

    cudaFuncSetAttribute(proj_kernel, cudaFuncAttributeMaxDynamicSharedMemorySize, PROJ_SMEM);
    cudaFuncSetAttribute(out_kernel, cudaFuncAttributeMaxDynamicSharedMemorySize, OSMEM_BYTES);

    // proj kept as 4th launch (ncu capture slot)
    prep_misc_kernel<<<(BATCHN * NH * HD * HD + 255) / 256, 256>>>();
    prep_w_kernel<<<2 * DIMC * KPROJ / 256, 256>>>(qk_w);
    xhalf_kernel<<<BATCHN * DIMC * NPOS / 8 / 256, 256>>>(x);
    proj_kernel<<<dim3(8, 8, 2 * BATCHN), 256, PROJ_SMEM>>>(qk_b);
    kv_kernel<<<dim3(BATCHN * NH, 4), 256>>>(x);
    out_kernel<<<dim3(8, BATCHN * NH), 512, OSMEM_BYTES>>>(out, x, lepe_w, lepe_b);
}

// round 12
// speedup vs baseline: 1.0888x; 1.0888x over previous
#include <cuda_runtime.h>
#include <cuda_fp16.h>
#include <cstdint>
#include <math.h>

#define DIMC 1024
#define NH   16
#define HD   64
#define NPOS 1024
#define BATCHN 16
#define KPROJ 512

// ---------------- scratch ----------------
__device__ __half g_wf16[2 * DIMC * KPROJ];                 // W rounded fp16
__device__ __half g_xh[BATCHN * DIMC * NPOS];               // x fp16, native [b][c][p]
__device__ __half g_qh[BATCHN * DIMC * NPOS];               // unroped q fp16 [b][o][p]
__device__ __half g_kh[BATCHN * DIMC * NPOS];               // unroped k
__device__ float g_km[BATCHN * DIMC];
__device__ float g_kv[BATCHN * NH * HD * HD];               // [bh][e][d] fp32 accum
__device__ float g_cos[(DIMC / 2) * NPOS];                  // [j][p]
__device__ float g_sin[(DIMC / 2) * NPOS];

// ---------------- helpers ----------------
__device__ __forceinline__ void mmaf16(float c[4], const uint32_t a[4], const uint32_t b[2]) {
    asm volatile(
        "mma.sync.aligned.m16n8k16.row.col.f32.f16.f16.f32 "
        "{%0,%1,%2,%3}, {%4,%5,%6,%7}, {%8,%9}, {%0,%1,%2,%3};"
        : "+f"(c[0]), "+f"(c[1]), "+f"(c[2]), "+f"(c[3])
        : "r"(a[0]), "r"(a[1]), "r"(a[2]), "r"(a[3]), "r"(b[0]), "r"(b[1]));
}

__device__ __forceinline__ void splith(float v, __half& hi, __half& lo) {
    hi = __float2half_rn(v);
    lo = __float2half_rn(v - __half2float(hi));
}

__device__ __forceinline__ uint32_t packh(__half a, __half b) {
    return (uint32_t)__half_as_ushort(a) | ((uint32_t)__half_as_ushort(b) << 16);
}

__device__ __forceinline__ float elu1(float v) { return v > 0.f ? v + 1.f : expf(v); }

__device__ __forceinline__ uint32_t cvta_sm(const void* p) {
    return (uint32_t)__cvta_generic_to_shared(p);
}

__device__ __forceinline__ void cp16(uint32_t saddr, const void* g) {
    asm volatile("cp.async.cg.shared.global [%0], [%1], 16;" :: "r"(saddr), "l"(g));
}

__device__ __forceinline__ void ldsm4(uint32_t r[4], uint32_t addr) {
    asm volatile("ldmatrix.sync.aligned.m8n8.x4.shared.b16 {%0,%1,%2,%3}, [%4];"
                 : "=r"(r[0]), "=r"(r[1]), "=r"(r[2]), "=r"(r[3]) : "r"(addr));
}

__device__ __forceinline__ void ldsm4t(uint32_t r[4], uint32_t addr) {
    asm volatile("ldmatrix.sync.aligned.m8n8.x4.trans.shared.b16 {%0,%1,%2,%3}, [%4];"
                 : "=r"(r[0]), "=r"(r[1]), "=r"(r[2]), "=r"(r[3]) : "r"(addr));
}

// ---------------- prep kernels ----------------
__global__ void prep_misc_kernel() {
    int idx = blockIdx.x * blockDim.x + threadIdx.x;
    if (idx < (DIMC / 2) * NPOS) {
        int j = idx >> 10, p = idx & (NPOS - 1);
        int jj = (j < 256) ? j : j - 256;
        float pos = (float)((j < 256) ? (p >> 5) : (p & 31));
        float theta = expf(-(float)jj * (9.210340371976184f / 256.f));
        float ang = pos * theta;
        float s, c;
        sincosf(ang, &s, &c);
        g_cos[idx] = c;
        g_sin[idx] = s;
    }
    if (idx < BATCHN * NH * HD * HD) g_kv[idx] = 0.f;
    if (idx < BATCHN * DIMC) g_km[idx] = 0.f;
}

__global__ void prep_w_kernel(const float* __restrict__ qk_w) {
    int idx = blockIdx.x * blockDim.x + threadIdx.x;
    if (idx < 2 * DIMC * KPROJ) g_wf16[idx] = __float2half_rn(qk_w[idx]);
}

// x fp32 -> fp16, layout preserved
__global__ __launch_bounds__(256) void xhalf_kernel(const float* __restrict__ x) {
    size_t i = (size_t)blockIdx.x * 256 + threadIdx.x;   // over 16M/8
    const float4* X4 = (const float4*)x;
    float4 a = X4[2 * i], b = X4[2 * i + 1];
    uint4 o;
    o.x = packh(__float2half_rn(a.x), __float2half_rn(a.y));
    o.y = packh(__float2half_rn(a.z), __float2half_rn(a.w));
    o.z = packh(__float2half_rn(b.x), __float2half_rn(b.y));
    o.w = packh(__float2half_rn(b.z), __float2half_rn(b.w));
    ((uint4*)g_xh)[i] = o;
}

// ---------------- projection GEMM: fp16, 4-stage pipeline, B from native [c][p] ----------------
#define PSTR 40
#define PB_STR 136
#define APLANE (128 * PSTR)                  // 5120
#define BPLANE (32 * PB_STR)                 // 4352
#define STG (APLANE + BPLANE)                // 9472
#define NSTAGE 4
#define PROJ_SMEM (NSTAGE * STG * 2)         // 75776 bytes

__global__ __launch_bounds__(256) void proj_kernel(const float* __restrict__ qk_b) {
    extern __shared__ __align__(16) __half sm[];

    int tid = threadIdx.x;
    int lane = tid & 31, wid = tid >> 5;
    int wm = wid >> 2, wn = wid & 3;
    int g4 = lane >> 2, tg = lane & 3;
    int arow = (lane & 7) + ((lane >> 3) & 1) * 8;
    int acol = (lane >> 4) * 8;

    int pt = blockIdx.x, ot = blockIdx.y;
    int b = blockIdx.z >> 1, grp = blockIdx.z & 1;
    const __half* W = g_wf16 + (size_t)grp * DIMC * KPROJ;
    const __half* Xc = g_xh + ((size_t)b * DIMC + grp * KPROJ) * NPOS;
    int o0 = ot * 128, p0 = pt * 128;

    float c[4][4][4];
#pragma unroll
    for (int i = 0; i < 4; i++)
#pragma unroll
        for (int j = 0; j < 4; j++)
#pragma unroll
            for (int k = 0; k < 4; k++) c[i][j][k] = 0.f;

    int so = tid >> 2;
    int scs = (tid & 3) * 8;
    const __half* Wg = W + (size_t)(o0 + so) * KPROJ + scs;
    uint32_t smem_base = cvta_sm(sm);

    auto issue = [&](int kt) {
        uint32_t st = smem_base + ((kt & (NSTAGE - 1)) * STG) * 2;
        int c0 = kt * 32;
        // A: W rows o (128 x 32)
        cp16(st + (so * PSTR + scs) * 2, Wg + c0);
        cp16(st + ((so + 64) * PSTR + scs) * 2, Wg + (size_t)64 * KPROJ + c0);
        // B: X rows c (32 x 128), native layout
#pragma unroll
        for (int i = tid; i < 512; i += 256) {
            int row = i >> 4, ch = (i & 15) * 8;
            cp16(st + (APLANE + row * PB_STR + ch) * 2,
                 Xc + (size_t)(c0 + row) * NPOS + p0 + ch);
        }
    };

    issue(0);
    asm volatile("cp.async.commit_group;");
    issue(1);
    asm volatile("cp.async.commit_group;");
    issue(2);
    asm volatile("cp.async.commit_group;");

    for (int kt = 0; kt < 16; kt++) {
        if (kt < 14)       asm volatile("cp.async.wait_group 2;");
        else if (kt == 14) asm volatile("cp.async.wait_group 1;");
        else               asm volatile("cp.async.wait_group 0;");
        __syncthreads();

        uint32_t stA = smem_base + ((kt & (NSTAGE - 1)) * STG) * 2;
        uint32_t stB = stA + APLANE * 2;

#pragma unroll
        for (int ks = 0; ks < 2; ks++) {
            int kk = ks * 16;
            uint32_t a4[4][4];
#pragma unroll
            for (int mi = 0; mi < 4; mi++)
                ldsm4(a4[mi], stA + ((wm * 64 + mi * 16 + arow) * PSTR + kk + acol) * 2);
            uint32_t bf[4][2];
#pragma unroll
            for (int nip = 0; nip < 2; nip++) {
                uint32_t r[4];
                ldsm4t(r, stB + ((kk + arow) * PB_STR + wn * 32 + nip * 16 + acol) * 2);
                bf[2 * nip][0] = r[0]; bf[2 * nip][1] = r[1];
                bf[2 * nip + 1][0] = r[2]; bf[2 * nip + 1][1] = r[3];
            }
#pragma unroll
            for (int mi = 0; mi < 4; mi++)
#pragma unroll
                for (int ni = 0; ni < 4; ni++)
                    mmaf16(c[mi][ni], a4[mi], bf[ni]);
        }

        if (kt + 3 < 16) {
            issue(kt + 3);
            asm volatile("cp.async.commit_group;");
        }
    }

    // epilogue: bias + elu + 1, fp16 store (unroped), km atomics for k-group
    __half* dst = (grp ? g_kh : g_qh) + (size_t)b * DIMC * NPOS;
#pragma unroll
    for (int mi = 0; mi < 4; mi++) {
        int r0 = o0 + wm * 64 + mi * 16 + g4;
        int r1 = r0 + 8;
        float bias0 = __ldg(&qk_b[grp * DIMC + r0]);
        float bias1 = __ldg(&qk_b[grp * DIMC + r1]);
        float rs0 = 0.f, rs1 = 0.f;
#pragma unroll
        for (int ni = 0; ni < 4; ni++) {
            int p = p0 + wn * 32 + ni * 8 + tg * 2;
            float v00 = elu1(c[mi][ni][0] + bias0);
            float v01 = elu1(c[mi][ni][1] + bias0);
            float v10 = elu1(c[mi][ni][2] + bias1);
            float v11 = elu1(c[mi][ni][3] + bias1);
            *(uint32_t*)&dst[(size_t)r0 * NPOS + p] = packh(__float2half_rn(v00), __float2half_rn(v01));
            *(uint32_t*)&dst[(size_t)r1 * NPOS + p] = packh(__float2half_rn(v10), __float2half_rn(v11));
            rs0 += v00 + v01;
            rs1 += v10 + v11;
        }
        if (grp) {
            rs0 += __shfl_xor_sync(0xffffffffu, rs0, 1);
            rs0 += __shfl_xor_sync(0xffffffffu, rs0, 2);
            rs1 += __shfl_xor_sync(0xffffffffu, rs1, 1);
            rs1 += __shfl_xor_sync(0xffffffffu, rs1, 2);
            if (tg == 0) {
                atomicAdd(&g_km[b * DIMC + r0], rs0 * (1.f / NPOS));
                atomicAdd(&g_km[b * DIMC + r1], rs1 * (1.f / NPOS));
            }
        }
    }
}

// ---------------- kv kernel (n-split x8): rope k during staging, 2 MMAs ----------------
#define KV_STR 72

__global__ __launch_bounds__(256) void kv_kernel(const float* __restrict__ x) {
    __shared__ __align__(16) __half sa[64 * KV_STR];      // rope(k) [d][n]
    __shared__ __align__(16) __half sb[2][64 * KV_STR];   // v hi/lo [e][n]

    int tid = threadIdx.x;
    int lane = tid & 31, wid = tid >> 5;
    int wm = wid >> 2, wn = wid & 3;
    int g4 = lane >> 2, tg = lane & 3;
    int bh = blockIdx.x, chunk = blockIdx.y;
    int b = bh >> 4, h = bh & 15;
    size_t base = ((size_t)b * DIMC + h * HD) * NPOS;
    const __half* K = g_kh + base;
    const float* V = x + base;

    int kd2 = tid >> 3, kng = (tid & 7) * 8;
    int ve = tid >> 2, vng = (tid & 3) * 16;

    float c[2][2][4];
#pragma unroll
    for (int i = 0; i < 2; i++)
#pragma unroll
        for (int j = 0; j < 2; j++)
#pragma unroll
            for (int k = 0; k < 4; k++) c[i][j][k] = 0.f;

    for (int sub = 0; sub < 2; sub++) {
        int n0 = chunk * 128 + sub * 64;
        // stage rope(k): 8 n per thread
        {
            int r0 = 2 * kd2, r1 = r0 + 1;
            size_t o0 = (size_t)r0 * NPOS + n0 + kng;
            size_t o1 = o0 + NPOS;
            uint4 kh0 = *(const uint4*)&K[o0];
            uint4 kh1 = *(const uint4*)&K[o1];
            const __half* p0 = (const __half*)&kh0;
            const __half* p1 = (const __half*)&kh1;
            int j = h * 32 + kd2;
            const float* Cp = &g_cos[(size_t)j * NPOS + n0 + kng];
            const float* Sp = &g_sin[(size_t)j * NPOS + n0 + kng];
            float4 cA = *(const float4*)Cp, cB = *(const float4*)(Cp + 4);
            float4 sA = *(const float4*)Sp, sB = *(const float4*)(Sp + 4);
            float csv[8] = {cA.x, cA.y, cA.z, cA.w, cB.x, cB.y, cB.z, cB.w};
            float snv[8] = {sA.x, sA.y, sA.z, sA.w, sB.x, sB.y, sB.z, sB.w};
            __half oh0[8], oh1[8];
#pragma unroll
            for (int t = 0; t < 8; t++) {
                float k0 = __half2float(p0[t]);
                float k1 = __half2float(p1[t]);
                oh0[t] = __float2half_rn(csv[t] * k0 - snv[t] * k1);
                oh1[t] = __float2half_rn(snv[t] * k0 + csv[t] * k1);
            }
            *(uint4*)&sa[r0 * KV_STR + kng] = *(uint4*)oh0;
            *(uint4*)&sa[r1 * KV_STR + kng] = *(uint4*)oh1;
        }
        // stage v hi/lo: 16 n per thread
        {
            const float* Vp = &V[(size_t)ve * NPOS + n0 + vng];
            __half vh[16], vl[16];
#pragma unroll
            for (int t4 = 0; t4 < 4; t4++) {
                float4 v = *(const float4*)(Vp + t4 * 4);
                splith(v.x, vh[t4 * 4 + 0], vl[t4 * 4 + 0]);
                splith(v.y, vh[t4 * 4 + 1], vl[t4 * 4 + 1]);
                splith(v.z, vh[t4 * 4 + 2], vl[t4 * 4 + 2]);
                splith(v.w, vh[t4 * 4 + 3], vl[t4 * 4 + 3]);
            }
            *(uint4*)&sb[0][ve * KV_STR + vng] = *(uint4*)vh;
            *(uint4*)&sb[0][ve * KV_STR + vng + 8] = *(uint4*)(vh + 8);
            *(uint4*)&sb[1][ve * KV_STR + vng] = *(uint4*)vl;
            *(uint4*)&sb[1][ve * KV_STR + vng + 8] = *(uint4*)(vl + 8);
        }
        __syncthreads();

#pragma unroll
        for (int ks = 0; ks < 4; ks++) {
            int kk = ks * 16;
            int col = kk + tg * 2;
            uint32_t ah[2][4];
#pragma unroll
            for (int mi = 0; mi < 2; mi++) {
                int d = wm * 32 + mi * 16 + g4;
                ah[mi][0] = *(uint32_t*)&sa[d * KV_STR + col];
                ah[mi][1] = *(uint32_t*)&sa[(d + 8) * KV_STR + col];
                ah[mi][2] = *(uint32_t*)&sa[d * KV_STR + col + 8];
                ah[mi][3] = *(uint32_t*)&sa[(d + 8) * KV_STR + col + 8];
            }
            uint32_t bh2[2][2], bl2[2][2];
#pragma unroll
            for (int ni = 0; ni < 2; ni++) {
                int e = wn * 16 + ni * 8 + g4;
                bh2[ni][0] = *(uint32_t*)&sb[0][e * KV_STR + col];
                bh2[ni][1] = *(uint32_t*)&sb[0][e * KV_STR + col + 8];
                bl2[ni][0] = *(uint32_t*)&sb[1][e * KV_STR + col];
                bl2[ni][1] = *(uint32_t*)&sb[1][e * KV_STR + col + 8];
            }
#pragma unroll
            for (int mi = 0; mi < 2; mi++)
#pragma unroll
                for (int ni = 0; ni < 2; ni++) {
                    mmaf16(c[mi][ni], ah[mi], bh2[ni]);
                    mmaf16(c[mi][ni], ah[mi], bl2[ni]);
                }
        }
        __syncthreads();
    }

    float* KV = g_kv + (size_t)bh * HD * HD;
#pragma unroll
    for (int mi = 0; mi < 2; mi++) {
#pragma unroll
        for (int ni = 0; ni < 2; ni++) {
            int d0 = wm * 32 + mi * 16 + g4, d1 = d0 + 8;
            int e0 = wn * 16 + ni * 8 + tg * 2, e1 = e0 + 1;
            atomicAdd(&KV[e0 * HD + d0], c[mi][ni][0] * (1.f / NPOS));
            atomicAdd(&KV[e1 * HD + d0], c[mi][ni][1] * (1.f / NPOS));
            atomicAdd(&KV[e0 * HD + d1], c[mi][ni][2] * (1.f / NPOS));
            atomicAdd(&KV[e1 * HD + d1], c[mi][ni][3] * (1.f / NPOS));
        }
    }
}

// ---------------- out kernel: 512 threads, attn + fused lepe, rope q + z in staging ----------------
#define OA_STR 66
#define OB_STR 72
#define OSMEM_BYTES ((128 * OA_STR + 2 * 64 * OB_STR) * 2 + (128 + 576 + 64 + 64 * 198) * 4)

__global__ __launch_bounds__(512, 2) void out_kernel(float* __restrict__ out,
                                                     const float* __restrict__ x,
                                                     const float* __restrict__ lepe_w,
                                                     const float* __restrict__ lepe_b) {
    extern __shared__ __align__(16) char sm_raw[];
    __half* sa = (__half*)sm_raw;              // roped q [n][d] 128 x OA_STR
    __half* skh = sa + 128 * OA_STR;
    __half* skl = skh + 64 * OB_STR;
    float* s_z = (float*)(skl + 64 * OB_STR);
    float* sw = s_z + 128;
    float* sbias = sw + 576;
    float* sx = sbias + 64;

    int tid = threadIdx.x;
    int lane = tid & 31, wid = tid >> 5;
    int wm = wid >> 2, wn = wid & 3;           // 4 n-groups x 4 e-groups
    int g4 = lane >> 2, tg = lane & 3;

    int nt = blockIdx.x, bh = blockIdx.y;
    int b = bh >> 4, h = bh & 15;
    int n0 = nt * 128;
    int y0 = nt * 4;
    size_t qbase = ((size_t)b * DIMC + h * HD) * NPOS;
    const __half* Q = g_qh + qbase;
    const float* km = g_km + b * DIMC + h * HD;

    if (tid < 128) s_z[tid] = 0.f;
    // stage kv hi/lo
    {
        const float* KV = g_kv + (size_t)bh * HD * HD;
        for (int i = tid; i < 4096; i += 512) {
            int e = i >> 6, d = i & 63;
            __half hi, lo;
            splith(KV[i], hi, lo);
            skh[e * OB_STR + d] = hi;
            skl[e * OB_STR + d] = lo;
        }
    }
    // stage lepe weights/bias
    for (int i = tid; i < 576; i += 512) sw[i] = __ldg(&lepe_w[h * 576 + i]);
    if (tid < 64) sbias[tid] = __ldg(&lepe_b[h * 64 + tid]);
    // stage x halo rows
    {
        const float* Xp = x + qbase;
#pragma unroll
        for (int rr = 0; rr < 6; rr++) {
            int yy = y0 - 1 + rr;
            bool valid = (yy >= 0) && (yy < 32);
            int i = tid;
            if (i < 512) {
                int e = i >> 3, q4 = (i & 7) * 4;
                float4 v = make_float4(0.f, 0.f, 0.f, 0.f);
                if (valid) v = *(const float4*)&Xp[(size_t)e * 1024 + yy * 32 + q4];
                float* d = &sx[e * 198 + rr * 33 + q4];
                d[0] = v.x; d[1] = v.y; d[2] = v.z; d[3] = v.w;
            }
        }
    }
    __syncthreads();

    // stage rope(q) + z partial: 4 thread-quarters cover d2 0..31 over 8 passes
    float zacc = 0.f;
    int nfix = tid & 127;
    int quarter = tid >> 7;
#pragma unroll 4
    for (int pass = 0; pass < 8; pass++) {
        int d2 = quarter + pass * 4;
        size_t i0 = (size_t)(2 * d2) * NPOS + n0 + nfix;
        size_t i1 = i0 + NPOS;
        float q0 = __half2float(Q[i0]);
        float q1 = __half2float(Q[i1]);
        float km0 = __ldg(&km[2 * d2]);
        float km1 = __ldg(&km[2 * d2 + 1]);
        zacc += q0 * km0 + q1 * km1;
        int j = h * 32 + d2;
        float cs = g_cos[(size_t)j * NPOS + n0 + nfix];
        float sn = g_sin[(size_t)j * NPOS + n0 + nfix];
        float r0 = cs * q0 - sn * q1;
        float r1 = sn * q0 + cs * q1;
        *(uint32_t*)&sa[nfix * OA_STR + 2 * d2] = packh(__float2half_rn(r0), __float2half_rn(r1));
    }
    atomicAdd(&s_z[nfix], zacc);
    __syncthreads();

    float c[2][2][4];
#pragma unroll
    for (int i = 0; i < 2; i++)
#pragma unroll
        for (int j = 0; j < 2; j++)
#pragma unroll
            for (int k = 0; k < 4; k++) c[i][j][k] = 0.f;

#pragma unroll
    for (int ks = 0; ks < 4; ks++) {
        int kk = ks * 16;
        int col = kk + tg * 2;
        uint32_t ah[2][4];
#pragma unroll
        for (int mi = 0; mi < 2; mi++) {
            int n = wm * 32 + mi * 16 + g4;
            ah[mi][0] = *(uint32_t*)&sa[n * OA_STR + col];
            ah[mi][1] = *(uint32_t*)&sa[(n + 8) * OA_STR + col];
            ah[mi][2] = *(uint32_t*)&sa[n * OA_STR + col + 8];
            ah[mi][3] = *(uint32_t*)&sa[(n + 8) * OA_STR + col + 8];
        }
        uint32_t bh2[2][2], bl2[2][2];
#pragma unroll
        for (int ni = 0; ni < 2; ni++) {
            int e = wn * 16 + ni * 8 + g4;
            bh2[ni][0] = *(uint32_t*)&skh[e * OB_STR + col];
            bh2[ni][1] = *(uint32_t*)&skh[e * OB_STR + col + 8];
            bl2[ni][0] = *(uint32_t*)&skl[e * OB_STR + col];
            bl2[ni][1] = *(uint32_t*)&skl[e * OB_STR + col + 8];
        }
#pragma unroll
        for (int mi = 0; mi < 2; mi++)
#pragma unroll
            for (int ni = 0; ni < 2; ni++) {
                mmaf16(c[mi][ni], ah[mi], bh2[ni]);
                mmaf16(c[mi][ni], ah[mi], bl2[ni]);
            }
    }

    // epilogue: z scale + fused lepe stencil
    float* O = out + qbase;
#pragma unroll
    for (int ni = 0; ni < 2; ni++) {
        int e0 = wn * 16 + ni * 8 + tg * 2;
        int e1 = e0 + 1;
        float b0 = sbias[e0], b1 = sbias[e1];

        auto lepe_at = [&](int e, float bs, int nr) -> float {
            int yloc = nr >> 5, xx = nr & 31;
            const float* base = &sx[e * 198 + yloc * 33];
            const float* wv = &sw[e * 9];
            float acc = bs;
#pragma unroll
            for (int i = 0; i < 3; i++) {
                const float* rw = base + i * 33;
                acc += wv[i * 3 + 1] * rw[xx];
                if (xx > 0)  acc += wv[i * 3 + 0] * rw[xx - 1];
                if (xx < 31) acc += wv[i * 3 + 2] * rw[xx + 1];
            }
            return acc;
        };

#pragma unroll
        for (int mi = 0; mi < 2; mi++) {
            int nr0 = wm * 32 + mi * 16 + g4;
            int nr1 = nr0 + 8;
            float z0 = 1.f / (s_z[nr0] + 1e-6f);
            float z1 = 1.f / (s_z[nr1] + 1e-6f);
            size_t i00 = (size_t)e0 * NPOS + n0 + nr0;
            size_t i01 = (size_t)e1 * NPOS + n0 + nr0;
            size_t i10 = (size_t)e0 * NPOS + n0 + nr1;
            size_t i11 = (size_t)e1 * NPOS + n0 + nr1;
            O[i00] = c[mi][ni][0] * z0 + lepe_at(e0, b0, nr0);
            O[i01] = c[mi][ni][1] * z0 + lepe_at(e1, b1, nr0);
            O[i10] = c[mi][ni][2] * z1 + lepe_at(e0, b0, nr1);
            O[i11] = c[mi][ni][3] * z1 + lepe_at(e1, b1, nr1);
        }
    }
}

// ---------------- launch ----------------
extern "C" void kernel_launch(void* const* d_in, const int* in_sizes, int n_in,
                              void* d_out, int out_size) {
    const float* x      = (const float*)d_in[0];
    const float* qk_w   = (const float*)d_in[1];
    const float* qk_b   = (const float*)d_in[2];
    const float* lepe_w = (const float*)d_in[3];
    const float* lepe_b = (const float*)d_in[4];
    float* out = (float*)d_out;

    cudaFuncSetAttribute(proj_kernel, cudaFuncAttributeMaxDynamicSharedMemorySize, PROJ_SMEM);
    cudaFuncSetAttribute(out_kernel, cudaFuncAttributeMaxDynamicSharedMemorySize, OSMEM_BYTES);

    // proj kept as 4th launch (ncu capture slot)
    prep_misc_kernel<<<(BATCHN * NH * HD * HD + 255) / 256, 256>>>();
    prep_w_kernel<<<2 * DIMC * KPROJ / 256, 256>>>(qk_w);
    xhalf_kernel<<<BATCHN * DIMC * NPOS / 8 / 256, 256>>>(x);
    proj_kernel<<<dim3(8, 8, 2 * BATCHN), 256, PROJ_SMEM>>>(qk_b);
    kv_kernel<<<dim3(BATCHN * NH, 8), 256>>>(x);
    out_kernel<<<dim3(8, BATCHN * NH), 512, OSMEM_BYTES>>>(out, x, lepe_w, lepe_b);
}

// round 13
// speedup vs baseline: 1.1168x; 1.0256x over previous
#include <cuda_runtime.h>
#include <cuda_fp16.h>
#include <cstdint>
#include <math.h>

#define DIMC 1024
#define NH   16
#define HD   64
#define NPOS 1024
#define BATCHN 16
#define KPROJ 512

// ---------------- scratch ----------------
__device__ __half g_wf16[2 * DIMC * KPROJ];                 // W rounded fp16
__device__ __half g_xh[BATCHN * DIMC * NPOS];               // x fp16, native [b][c][p]
__device__ __half g_qh[BATCHN * DIMC * NPOS];               // unroped q fp16 [b][o][p]
__device__ __half g_kh[BATCHN * DIMC * NPOS];               // unroped k
__device__ float g_km[BATCHN * DIMC];
__device__ float g_kv[BATCHN * NH * HD * HD];               // [bh][e][d] fp32 accum
__device__ float g_cos[(DIMC / 2) * NPOS];                  // [j][p]
__device__ float g_sin[(DIMC / 2) * NPOS];

// ---------------- helpers ----------------
__device__ __forceinline__ void mmaf16(float c[4], const uint32_t a[4], const uint32_t b[2]) {
    asm volatile(
        "mma.sync.aligned.m16n8k16.row.col.f32.f16.f16.f32 "
        "{%0,%1,%2,%3}, {%4,%5,%6,%7}, {%8,%9}, {%0,%1,%2,%3};"
        : "+f"(c[0]), "+f"(c[1]), "+f"(c[2]), "+f"(c[3])
        : "r"(a[0]), "r"(a[1]), "r"(a[2]), "r"(a[3]), "r"(b[0]), "r"(b[1]));
}

__device__ __forceinline__ void splith(float v, __half& hi, __half& lo) {
    hi = __float2half_rn(v);
    lo = __float2half_rn(v - __half2float(hi));
}

__device__ __forceinline__ uint32_t packh(__half a, __half b) {
    return (uint32_t)__half_as_ushort(a) | ((uint32_t)__half_as_ushort(b) << 16);
}

__device__ __forceinline__ float elu1(float v) { return v > 0.f ? v + 1.f : expf(v); }

__device__ __forceinline__ uint32_t cvta_sm(const void* p) {
    return (uint32_t)__cvta_generic_to_shared(p);
}

__device__ __forceinline__ void cp16(uint32_t saddr, const void* g) {
    asm volatile("cp.async.cg.shared.global [%0], [%1], 16;" :: "r"(saddr), "l"(g));
}

__device__ __forceinline__ void ldsm4(uint32_t r[4], uint32_t addr) {
    asm volatile("ldmatrix.sync.aligned.m8n8.x4.shared.b16 {%0,%1,%2,%3}, [%4];"
                 : "=r"(r[0]), "=r"(r[1]), "=r"(r[2]), "=r"(r[3]) : "r"(addr));
}

__device__ __forceinline__ void ldsm4t(uint32_t r[4], uint32_t addr) {
    asm volatile("ldmatrix.sync.aligned.m8n8.x4.trans.shared.b16 {%0,%1,%2,%3}, [%4];"
                 : "=r"(r[0]), "=r"(r[1]), "=r"(r[2]), "=r"(r[3]) : "r"(addr));
}

// ---------------- prep kernels ----------------
__global__ void prep_misc_kernel() {
    int idx = blockIdx.x * blockDim.x + threadIdx.x;
    if (idx < (DIMC / 2) * NPOS) {
        int j = idx >> 10, p = idx & (NPOS - 1);
        int jj = (j < 256) ? j : j - 256;
        float pos = (float)((j < 256) ? (p >> 5) : (p & 31));
        float theta = expf(-(float)jj * (9.210340371976184f / 256.f));
        float ang = pos * theta;
        float s, c;
        sincosf(ang, &s, &c);
        g_cos[idx] = c;
        g_sin[idx] = s;
    }
    if (idx < BATCHN * NH * HD * HD) g_kv[idx] = 0.f;
    if (idx < BATCHN * DIMC) g_km[idx] = 0.f;
}

__global__ void prep_w_kernel(const float* __restrict__ qk_w) {
    int idx = blockIdx.x * blockDim.x + threadIdx.x;
    if (idx < 2 * DIMC * KPROJ) g_wf16[idx] = __float2half_rn(qk_w[idx]);
}

// x fp32 -> fp16, layout preserved
__global__ __launch_bounds__(256) void xhalf_kernel(const float* __restrict__ x) {
    size_t i = (size_t)blockIdx.x * 256 + threadIdx.x;   // over 16M/8
    const float4* X4 = (const float4*)x;
    float4 a = X4[2 * i], b = X4[2 * i + 1];
    uint4 o;
    o.x = packh(__float2half_rn(a.x), __float2half_rn(a.y));
    o.y = packh(__float2half_rn(a.z), __float2half_rn(a.w));
    o.z = packh(__float2half_rn(b.x), __float2half_rn(b.y));
    o.w = packh(__float2half_rn(b.z), __float2half_rn(b.w));
    ((uint4*)g_xh)[i] = o;
}

// ---------------- projection GEMM: fp16, 4-stage pipeline, B from native [c][p] ----------------
#define PSTR 40
#define PB_STR 136
#define APLANE (128 * PSTR)                  // 5120
#define BPLANE (32 * PB_STR)                 // 4352
#define STG (APLANE + BPLANE)                // 9472
#define NSTAGE 4
#define PROJ_SMEM (NSTAGE * STG * 2)         // 75776 bytes

__global__ __launch_bounds__(256) void proj_kernel(const float* __restrict__ qk_b) {
    extern __shared__ __align__(16) __half sm[];

    int tid = threadIdx.x;
    int lane = tid & 31, wid = tid >> 5;
    int wm = wid >> 2, wn = wid & 3;
    int g4 = lane >> 2, tg = lane & 3;
    int arow = (lane & 7) + ((lane >> 3) & 1) * 8;
    int acol = (lane >> 4) * 8;

    int pt = blockIdx.x, ot = blockIdx.y;
    int b = blockIdx.z >> 1, grp = blockIdx.z & 1;
    const __half* W = g_wf16 + (size_t)grp * DIMC * KPROJ;
    const __half* Xc = g_xh + ((size_t)b * DIMC + grp * KPROJ) * NPOS;
    int o0 = ot * 128, p0 = pt * 128;

    float c[4][4][4];
#pragma unroll
    for (int i = 0; i < 4; i++)
#pragma unroll
        for (int j = 0; j < 4; j++)
#pragma unroll
            for (int k = 0; k < 4; k++) c[i][j][k] = 0.f;

    int so = tid >> 2;
    int scs = (tid & 3) * 8;
    const __half* Wg = W + (size_t)(o0 + so) * KPROJ + scs;
    uint32_t smem_base = cvta_sm(sm);

    auto issue = [&](int kt) {
        uint32_t st = smem_base + ((kt & (NSTAGE - 1)) * STG) * 2;
        int c0 = kt * 32;
        cp16(st + (so * PSTR + scs) * 2, Wg + c0);
        cp16(st + ((so + 64) * PSTR + scs) * 2, Wg + (size_t)64 * KPROJ + c0);
#pragma unroll
        for (int i = tid; i < 512; i += 256) {
            int row = i >> 4, ch = (i & 15) * 8;
            cp16(st + (APLANE + row * PB_STR + ch) * 2,
                 Xc + (size_t)(c0 + row) * NPOS + p0 + ch);
        }
    };

    issue(0);
    asm volatile("cp.async.commit_group;");
    issue(1);
    asm volatile("cp.async.commit_group;");
    issue(2);
    asm volatile("cp.async.commit_group;");

    for (int kt = 0; kt < 16; kt++) {
        if (kt < 14)       asm volatile("cp.async.wait_group 2;");
        else if (kt == 14) asm volatile("cp.async.wait_group 1;");
        else               asm volatile("cp.async.wait_group 0;");
        __syncthreads();

        uint32_t stA = smem_base + ((kt & (NSTAGE - 1)) * STG) * 2;
        uint32_t stB = stA + APLANE * 2;

#pragma unroll
        for (int ks = 0; ks < 2; ks++) {
            int kk = ks * 16;
            uint32_t a4[4][4];
#pragma unroll
            for (int mi = 0; mi < 4; mi++)
                ldsm4(a4[mi], stA + ((wm * 64 + mi * 16 + arow) * PSTR + kk + acol) * 2);
            uint32_t bf[4][2];
#pragma unroll
            for (int nip = 0; nip < 2; nip++) {
                uint32_t r[4];
                ldsm4t(r, stB + ((kk + arow) * PB_STR + wn * 32 + nip * 16 + acol) * 2);
                bf[2 * nip][0] = r[0]; bf[2 * nip][1] = r[1];
                bf[2 * nip + 1][0] = r[2]; bf[2 * nip + 1][1] = r[3];
            }
#pragma unroll
            for (int mi = 0; mi < 4; mi++)
#pragma unroll
                for (int ni = 0; ni < 4; ni++)
                    mmaf16(c[mi][ni], a4[mi], bf[ni]);
        }

        if (kt + 3 < 16) {
            issue(kt + 3);
            asm volatile("cp.async.commit_group;");
        }
    }

    // epilogue: bias + elu + 1, fp16 store (unroped), km atomics for k-group
    __half* dst = (grp ? g_kh : g_qh) + (size_t)b * DIMC * NPOS;
#pragma unroll
    for (int mi = 0; mi < 4; mi++) {
        int r0 = o0 + wm * 64 + mi * 16 + g4;
        int r1 = r0 + 8;
        float bias0 = __ldg(&qk_b[grp * DIMC + r0]);
        float bias1 = __ldg(&qk_b[grp * DIMC + r1]);
        float rs0 = 0.f, rs1 = 0.f;
#pragma unroll
        for (int ni = 0; ni < 4; ni++) {
            int p = p0 + wn * 32 + ni * 8 + tg * 2;
            float v00 = elu1(c[mi][ni][0] + bias0);
            float v01 = elu1(c[mi][ni][1] + bias0);
            float v10 = elu1(c[mi][ni][2] + bias1);
            float v11 = elu1(c[mi][ni][3] + bias1);
            *(uint32_t*)&dst[(size_t)r0 * NPOS + p] = packh(__float2half_rn(v00), __float2half_rn(v01));
            *(uint32_t*)&dst[(size_t)r1 * NPOS + p] = packh(__float2half_rn(v10), __float2half_rn(v11));
            rs0 += v00 + v01;
            rs1 += v10 + v11;
        }
        if (grp) {
            rs0 += __shfl_xor_sync(0xffffffffu, rs0, 1);
            rs0 += __shfl_xor_sync(0xffffffffu, rs0, 2);
            rs1 += __shfl_xor_sync(0xffffffffu, rs1, 1);
            rs1 += __shfl_xor_sync(0xffffffffu, rs1, 2);
            if (tg == 0) {
                atomicAdd(&g_km[b * DIMC + r0], rs0 * (1.f / NPOS));
                atomicAdd(&g_km[b * DIMC + r1], rs1 * (1.f / NPOS));
            }
        }
    }
}

// ---------------- kv kernel (n-split x8): rope k staging, fp16 V, 1 MMA ----------------
#define KV_STR 72

__global__ __launch_bounds__(256) void kv_kernel() {
    __shared__ __align__(16) __half sa[64 * KV_STR];      // rope(k) [d][n]
    __shared__ __align__(16) __half sb[64 * KV_STR];      // v fp16  [e][n]

    int tid = threadIdx.x;
    int lane = tid & 31, wid = tid >> 5;
    int wm = wid >> 2, wn = wid & 3;
    int g4 = lane >> 2, tg = lane & 3;
    int bh = blockIdx.x, chunk = blockIdx.y;
    int b = bh >> 4, h = bh & 15;
    size_t base = ((size_t)b * DIMC + h * HD) * NPOS;
    const __half* K = g_kh + base;
    const __half* V = g_xh + base;

    int kd2 = tid >> 3, kng = (tid & 7) * 8;
    int ve = tid >> 2, vng = (tid & 3) * 16;

    float c[2][2][4];
#pragma unroll
    for (int i = 0; i < 2; i++)
#pragma unroll
        for (int j = 0; j < 2; j++)
#pragma unroll
            for (int k = 0; k < 4; k++) c[i][j][k] = 0.f;

    for (int sub = 0; sub < 2; sub++) {
        int n0 = chunk * 128 + sub * 64;
        // stage rope(k): 8 n per thread
        {
            int r0 = 2 * kd2, r1 = r0 + 1;
            size_t o0 = (size_t)r0 * NPOS + n0 + kng;
            size_t o1 = o0 + NPOS;
            uint4 kh0 = *(const uint4*)&K[o0];
            uint4 kh1 = *(const uint4*)&K[o1];
            const __half* p0 = (const __half*)&kh0;
            const __half* p1 = (const __half*)&kh1;
            int j = h * 32 + kd2;
            const float* Cp = &g_cos[(size_t)j * NPOS + n0 + kng];
            const float* Sp = &g_sin[(size_t)j * NPOS + n0 + kng];
            float4 cA = *(const float4*)Cp, cB = *(const float4*)(Cp + 4);
            float4 sA = *(const float4*)Sp, sB = *(const float4*)(Sp + 4);
            float csv[8] = {cA.x, cA.y, cA.z, cA.w, cB.x, cB.y, cB.z, cB.w};
            float snv[8] = {sA.x, sA.y, sA.z, sA.w, sB.x, sB.y, sB.z, sB.w};
            __half oh0[8], oh1[8];
#pragma unroll
            for (int t = 0; t < 8; t++) {
                float k0 = __half2float(p0[t]);
                float k1 = __half2float(p1[t]);
                oh0[t] = __float2half_rn(csv[t] * k0 - snv[t] * k1);
                oh1[t] = __float2half_rn(snv[t] * k0 + csv[t] * k1);
            }
            *(uint4*)&sa[r0 * KV_STR + kng] = *(uint4*)oh0;
            *(uint4*)&sa[r1 * KV_STR + kng] = *(uint4*)oh1;
        }
        // stage v: straight fp16 vector copy, 16 n per thread
        {
            const __half* Vp = &V[(size_t)ve * NPOS + n0 + vng];
            *(uint4*)&sb[ve * KV_STR + vng] = *(const uint4*)Vp;
            *(uint4*)&sb[ve * KV_STR + vng + 8] = *(const uint4*)(Vp + 8);
        }
        __syncthreads();

#pragma unroll
        for (int ks = 0; ks < 4; ks++) {
            int kk = ks * 16;
            int col = kk + tg * 2;
            uint32_t ah[2][4];
#pragma unroll
            for (int mi = 0; mi < 2; mi++) {
                int d = wm * 32 + mi * 16 + g4;
                ah[mi][0] = *(uint32_t*)&sa[d * KV_STR + col];
                ah[mi][1] = *(uint32_t*)&sa[(d + 8) * KV_STR + col];
                ah[mi][2] = *(uint32_t*)&sa[d * KV_STR + col + 8];
                ah[mi][3] = *(uint32_t*)&sa[(d + 8) * KV_STR + col + 8];
            }
            uint32_t bv[2][2];
#pragma unroll
            for (int ni = 0; ni < 2; ni++) {
                int e = wn * 16 + ni * 8 + g4;
                bv[ni][0] = *(uint32_t*)&sb[e * KV_STR + col];
                bv[ni][1] = *(uint32_t*)&sb[e * KV_STR + col + 8];
            }
#pragma unroll
            for (int mi = 0; mi < 2; mi++)
#pragma unroll
                for (int ni = 0; ni < 2; ni++)
                    mmaf16(c[mi][ni], ah[mi], bv[ni]);
        }
        __syncthreads();
    }

    float* KV = g_kv + (size_t)bh * HD * HD;
#pragma unroll
    for (int mi = 0; mi < 2; mi++) {
#pragma unroll
        for (int ni = 0; ni < 2; ni++) {
            int d0 = wm * 32 + mi * 16 + g4, d1 = d0 + 8;
            int e0 = wn * 16 + ni * 8 + tg * 2, e1 = e0 + 1;
            atomicAdd(&KV[e0 * HD + d0], c[mi][ni][0] * (1.f / NPOS));
            atomicAdd(&KV[e1 * HD + d0], c[mi][ni][1] * (1.f / NPOS));
            atomicAdd(&KV[e0 * HD + d1], c[mi][ni][2] * (1.f / NPOS));
            atomicAdd(&KV[e1 * HD + d1], c[mi][ni][3] * (1.f / NPOS));
        }
    }
}

// ---------------- out kernel: 512 threads, attn + fused lepe, rope q + z in staging ----------------
#define OA_STR 66
#define OB_STR 72
#define OSMEM_BYTES ((128 * OA_STR + 2 * 64 * OB_STR) * 2 + (128 + 576 + 64 + 64 * 198) * 4)

__global__ __launch_bounds__(512, 2) void out_kernel(float* __restrict__ out,
                                                     const float* __restrict__ x,
                                                     const float* __restrict__ lepe_w,
                                                     const float* __restrict__ lepe_b) {
    extern __shared__ __align__(16) char sm_raw[];
    __half* sa = (__half*)sm_raw;              // roped q [n][d] 128 x OA_STR
    __half* skh = sa + 128 * OA_STR;
    __half* skl = skh + 64 * OB_STR;
    float* s_z = (float*)(skl + 64 * OB_STR);
    float* sw = s_z + 128;
    float* sbias = sw + 576;
    float* sx = sbias + 64;

    int tid = threadIdx.x;
    int lane = tid & 31, wid = tid >> 5;
    int wm = wid >> 2, wn = wid & 3;           // 4 n-groups x 4 e-groups
    int g4 = lane >> 2, tg = lane & 3;

    int nt = blockIdx.x, bh = blockIdx.y;
    int b = bh >> 4, h = bh & 15;
    int n0 = nt * 128;
    int y0 = nt * 4;
    size_t qbase = ((size_t)b * DIMC + h * HD) * NPOS;
    const __half* Q = g_qh + qbase;
    const float* km = g_km + b * DIMC + h * HD;

    if (tid < 128) s_z[tid] = 0.f;
    // stage kv hi/lo
    {
        const float* KV = g_kv + (size_t)bh * HD * HD;
        for (int i = tid; i < 4096; i += 512) {
            int e = i >> 6, d = i & 63;
            __half hi, lo;
            splith(KV[i], hi, lo);
            skh[e * OB_STR + d] = hi;
            skl[e * OB_STR + d] = lo;
        }
    }
    // stage lepe weights/bias
    for (int i = tid; i < 576; i += 512) sw[i] = __ldg(&lepe_w[h * 576 + i]);
    if (tid < 64) sbias[tid] = __ldg(&lepe_b[h * 64 + tid]);
    // stage x halo rows
    {
        const float* Xp = x + qbase;
#pragma unroll
        for (int rr = 0; rr < 6; rr++) {
            int yy = y0 - 1 + rr;
            bool valid = (yy >= 0) && (yy < 32);
            int i = tid;
            if (i < 512) {
                int e = i >> 3, q4 = (i & 7) * 4;
                float4 v = make_float4(0.f, 0.f, 0.f, 0.f);
                if (valid) v = *(const float4*)&Xp[(size_t)e * 1024 + yy * 32 + q4];
                float* d = &sx[e * 198 + rr * 33 + q4];
                d[0] = v.x; d[1] = v.y; d[2] = v.z; d[3] = v.w;
            }
        }
    }
    __syncthreads();

    // stage rope(q) + z partial: 4 thread-quarters cover d2 0..31 over 8 passes
    float zacc = 0.f;
    int nfix = tid & 127;
    int quarter = tid >> 7;
#pragma unroll 4
    for (int pass = 0; pass < 8; pass++) {
        int d2 = quarter + pass * 4;
        size_t i0 = (size_t)(2 * d2) * NPOS + n0 + nfix;
        size_t i1 = i0 + NPOS;
        float q0 = __half2float(Q[i0]);
        float q1 = __half2float(Q[i1]);
        float km0 = __ldg(&km[2 * d2]);
        float km1 = __ldg(&km[2 * d2 + 1]);
        zacc += q0 * km0 + q1 * km1;
        int j = h * 32 + d2;
        float cs = g_cos[(size_t)j * NPOS + n0 + nfix];
        float sn = g_sin[(size_t)j * NPOS + n0 + nfix];
        float r0 = cs * q0 - sn * q1;
        float r1 = sn * q0 + cs * q1;
        *(uint32_t*)&sa[nfix * OA_STR + 2 * d2] = packh(__float2half_rn(r0), __float2half_rn(r1));
    }
    atomicAdd(&s_z[nfix], zacc);
    __syncthreads();

    float c[2][2][4];
#pragma unroll
    for (int i = 0; i < 2; i++)
#pragma unroll
        for (int j = 0; j < 2; j++)
#pragma unroll
            for (int k = 0; k < 4; k++) c[i][j][k] = 0.f;

#pragma unroll
    for (int ks = 0; ks < 4; ks++) {
        int kk = ks * 16;
        int col = kk + tg * 2;
        uint32_t ah[2][4];
#pragma unroll
        for (int mi = 0; mi < 2; mi++) {
            int n = wm * 32 + mi * 16 + g4;
            ah[mi][0] = *(uint32_t*)&sa[n * OA_STR + col];
            ah[mi][1] = *(uint32_t*)&sa[(n + 8) * OA_STR + col];
            ah[mi][2] = *(uint32_t*)&sa[n * OA_STR + col + 8];
            ah[mi][3] = *(uint32_t*)&sa[(n + 8) * OA_STR + col + 8];
        }
        uint32_t bh2[2][2], bl2[2][2];
#pragma unroll
        for (int ni = 0; ni < 2; ni++) {
            int e = wn * 16 + ni * 8 + g4;
            bh2[ni][0] = *(uint32_t*)&skh[e * OB_STR + col];
            bh2[ni][1] = *(uint32_t*)&skh[e * OB_STR + col + 8];
            bl2[ni][0] = *(uint32_t*)&skl[e * OB_STR + col];
            bl2[ni][1] = *(uint32_t*)&skl[e * OB_STR + col + 8];
        }
#pragma unroll
        for (int mi = 0; mi < 2; mi++)
#pragma unroll
            for (int ni = 0; ni < 2; ni++) {
                mmaf16(c[mi][ni], ah[mi], bh2[ni]);
                mmaf16(c[mi][ni], ah[mi], bl2[ni]);
            }
    }

    // epilogue: z scale + fused lepe stencil
    float* O = out + qbase;
#pragma unroll
    for (int ni = 0; ni < 2; ni++) {
        int e0 = wn * 16 + ni * 8 + tg * 2;
        int e1 = e0 + 1;
        float b0 = sbias[e0], b1 = sbias[e1];

        auto lepe_at = [&](int e, float bs, int nr) -> float {
            int yloc = nr >> 5, xx = nr & 31;
            const float* base = &sx[e * 198 + yloc * 33];
            const float* wv = &sw[e * 9];
            float acc = bs;
#pragma unroll
            for (int i = 0; i < 3; i++) {
                const float* rw = base + i * 33;
                acc += wv[i * 3 + 1] * rw[xx];
                if (xx > 0)  acc += wv[i * 3 + 0] * rw[xx - 1];
                if (xx < 31) acc += wv[i * 3 + 2] * rw[xx + 1];
            }
            return acc;
        };

#pragma unroll
        for (int mi = 0; mi < 2; mi++) {
            int nr0 = wm * 32 + mi * 16 + g4;
            int nr1 = nr0 + 8;
            float z0 = 1.f / (s_z[nr0] + 1e-6f);
            float z1 = 1.f / (s_z[nr1] + 1e-6f);
            size_t i00 = (size_t)e0 * NPOS + n0 + nr0;
            size_t i01 = (size_t)e1 * NPOS + n0 + nr0;
            size_t i10 = (size_t)e0 * NPOS + n0 + nr1;
            size_t i11 = (size_t)e1 * NPOS + n0 + nr1;
            O[i00] = c[mi][ni][0] * z0 + lepe_at(e0, b0, nr0);
            O[i01] = c[mi][ni][1] * z0 + lepe_at(e1, b1, nr0);
            O[i10] = c[mi][ni][2] * z1 + lepe_at(e0, b0, nr1);
            O[i11] = c[mi][ni][3] * z1 + lepe_at(e1, b1, nr1);
        }
    }
}

// ---------------- launch ----------------
extern "C" void kernel_launch(void* const* d_in, const int* in_sizes, int n_in,
                              void* d_out, int out_size) {
    const float* x      = (const float*)d_in[0];
    const float* qk_w   = (const float*)d_in[1];
    const float* qk_b   = (const float*)d_in[2];
    const float* lepe_w = (const float*)d_in[3];
    const float* lepe_b = (const float*)d_in[4];
    float* out = (float*)d_out;

    cudaFuncSetAttribute(proj_kernel, cudaFuncAttributeMaxDynamicSharedMemorySize, PROJ_SMEM);
    cudaFuncSetAttribute(out_kernel, cudaFuncAttributeMaxDynamicSharedMemorySize, OSMEM_BYTES);

    // proj kept as 4th launch (ncu capture slot)
    prep_misc_kernel<<<(BATCHN * NH * HD * HD + 255) / 256, 256>>>();
    prep_w_kernel<<<2 * DIMC * KPROJ / 256, 256>>>(qk_w);
    xhalf_kernel<<<BATCHN * DIMC * NPOS / 8 / 256, 256>>>(x);
    proj_kernel<<<dim3(8, 8, 2 * BATCHN), 256, PROJ_SMEM>>>(qk_b);
    kv_kernel<<<dim3(BATCHN * NH, 8), 256>>>();
    out_kernel<<<dim3(8, BATCHN * NH), 512, OSMEM_BYTES>>>(out, x, lepe_w, lepe_b);
}

// round 14
// speedup vs baseline: 1.1497x; 1.0295x over previous
#include <cuda_runtime.h>
#include <cuda_fp16.h>
#include <cstdint>
#include <math.h>

#define DIMC 1024
#define NH   16
#define HD   64
#define NPOS 1024
#define BATCHN 16
#define KPROJ 512

// ---------------- scratch ----------------
__device__ __half g_wf16[2 * DIMC * KPROJ];                 // W rounded fp16
__device__ __half g_xh[BATCHN * DIMC * NPOS];               // x fp16, native [b][c][p]
__device__ __half g_qh[BATCHN * DIMC * NPOS];               // unroped q fp16 [b][o][p]
__device__ __half g_kh[BATCHN * DIMC * NPOS];               // unroped k
__device__ float g_km[BATCHN * DIMC];
__device__ float g_kv[BATCHN * NH * HD * HD];               // [bh][e][d] fp32 accum
__device__ float g_cos[(DIMC / 2) * NPOS];                  // [j][p]
__device__ float g_sin[(DIMC / 2) * NPOS];

// ---------------- helpers ----------------
__device__ __forceinline__ void mmaf16(float c[4], const uint32_t a[4], const uint32_t b[2]) {
    asm volatile(
        "mma.sync.aligned.m16n8k16.row.col.f32.f16.f16.f32 "
        "{%0,%1,%2,%3}, {%4,%5,%6,%7}, {%8,%9}, {%0,%1,%2,%3};"
        : "+f"(c[0]), "+f"(c[1]), "+f"(c[2]), "+f"(c[3])
        : "r"(a[0]), "r"(a[1]), "r"(a[2]), "r"(a[3]), "r"(b[0]), "r"(b[1]));
}

__device__ __forceinline__ void splith(float v, __half& hi, __half& lo) {
    hi = __float2half_rn(v);
    lo = __float2half_rn(v - __half2float(hi));
}

__device__ __forceinline__ uint32_t packh(__half a, __half b) {
    return (uint32_t)__half_as_ushort(a) | ((uint32_t)__half_as_ushort(b) << 16);
}

__device__ __forceinline__ float elu1(float v) { return v > 0.f ? v + 1.f : expf(v); }

__device__ __forceinline__ uint32_t cvta_sm(const void* p) {
    return (uint32_t)__cvta_generic_to_shared(p);
}

__device__ __forceinline__ void cp16(uint32_t saddr, const void* g) {
    asm volatile("cp.async.cg.shared.global [%0], [%1], 16;" :: "r"(saddr), "l"(g));
}

__device__ __forceinline__ void ldsm4(uint32_t r[4], uint32_t addr) {
    asm volatile("ldmatrix.sync.aligned.m8n8.x4.shared.b16 {%0,%1,%2,%3}, [%4];"
                 : "=r"(r[0]), "=r"(r[1]), "=r"(r[2]), "=r"(r[3]) : "r"(addr));
}

__device__ __forceinline__ void ldsm4t(uint32_t r[4], uint32_t addr) {
    asm volatile("ldmatrix.sync.aligned.m8n8.x4.trans.shared.b16 {%0,%1,%2,%3}, [%4];"
                 : "=r"(r[0]), "=r"(r[1]), "=r"(r[2]), "=r"(r[3]) : "r"(addr));
}

// ---------------- prep kernels ----------------
__global__ void prep_misc_kernel() {
    int idx = blockIdx.x * blockDim.x + threadIdx.x;
    if (idx < (DIMC / 2) * NPOS) {
        int j = idx >> 10, p = idx & (NPOS - 1);
        int jj = (j < 256) ? j : j - 256;
        float pos = (float)((j < 256) ? (p >> 5) : (p & 31));
        float theta = expf(-(float)jj * (9.210340371976184f / 256.f));
        float ang = pos * theta;
        float s, c;
        sincosf(ang, &s, &c);
        g_cos[idx] = c;
        g_sin[idx] = s;
    }
    if (idx < BATCHN * NH * HD * HD) g_kv[idx] = 0.f;
    if (idx < BATCHN * DIMC) g_km[idx] = 0.f;
}

__global__ void prep_w_kernel(const float* __restrict__ qk_w) {
    int idx = blockIdx.x * blockDim.x + threadIdx.x;
    if (idx < 2 * DIMC * KPROJ) g_wf16[idx] = __float2half_rn(qk_w[idx]);
}

// x fp32 -> fp16, layout preserved
__global__ __launch_bounds__(256) void xhalf_kernel(const float* __restrict__ x) {
    size_t i = (size_t)blockIdx.x * 256 + threadIdx.x;   // over 16M/8
    const float4* X4 = (const float4*)x;
    float4 a = X4[2 * i], b = X4[2 * i + 1];
    uint4 o;
    o.x = packh(__float2half_rn(a.x), __float2half_rn(a.y));
    o.y = packh(__float2half_rn(a.z), __float2half_rn(a.w));
    o.z = packh(__float2half_rn(b.x), __float2half_rn(b.y));
    o.w = packh(__float2half_rn(b.z), __float2half_rn(b.w));
    ((uint4*)g_xh)[i] = o;
}

// ---------------- projection GEMM: fp16, KCHUNK=64, 3-stage ring ----------------
#define PSTR 72
#define PB_STR 136
#define APLANE (128 * PSTR)                  // 9216
#define BPLANE (64 * PB_STR)                 // 8704
#define STG (APLANE + BPLANE)                // 17920 halves
#define NSTAGE 3
#define PROJ_SMEM (NSTAGE * STG * 2)         // 107520 bytes

__global__ __launch_bounds__(256) void proj_kernel(const float* __restrict__ qk_b) {
    extern __shared__ __align__(16) __half sm[];

    int tid = threadIdx.x;
    int lane = tid & 31, wid = tid >> 5;
    int wm = wid >> 2, wn = wid & 3;
    int g4 = lane >> 2, tg = lane & 3;
    int arow = (lane & 7) + ((lane >> 3) & 1) * 8;
    int acol = (lane >> 4) * 8;

    int pt = blockIdx.x, ot = blockIdx.y;
    int b = blockIdx.z >> 1, grp = blockIdx.z & 1;
    const __half* W = g_wf16 + (size_t)grp * DIMC * KPROJ;
    const __half* Xc = g_xh + ((size_t)b * DIMC + grp * KPROJ) * NPOS;
    int o0 = ot * 128, p0 = pt * 128;

    float c[4][4][4];
#pragma unroll
    for (int i = 0; i < 4; i++)
#pragma unroll
        for (int j = 0; j < 4; j++)
#pragma unroll
            for (int k = 0; k < 4; k++) c[i][j][k] = 0.f;

    uint32_t smem_base = cvta_sm(sm);

    auto issue = [&](int kt) {
        uint32_t st = smem_base + ((kt % NSTAGE) * STG) * 2;
        int c0 = kt * 64;
        // A: W 128 rows x 64 cols, 4 cp16 per thread
#pragma unroll
        for (int t = 0; t < 4; t++) {
            int i = tid + t * 256;
            int row = i >> 3, cs = (i & 7) * 8;
            cp16(st + (row * PSTR + cs) * 2, W + (size_t)(o0 + row) * KPROJ + c0 + cs);
        }
        // B: X 64 rows x 128 cols (native [c][p]), 4 cp16 per thread
#pragma unroll
        for (int t = 0; t < 4; t++) {
            int i = tid + t * 256;
            int row = i >> 4, ch = (i & 15) * 8;
            cp16(st + (APLANE + row * PB_STR + ch) * 2,
                 Xc + (size_t)(c0 + row) * NPOS + p0 + ch);
        }
    };

    issue(0);
    asm volatile("cp.async.commit_group;");
    issue(1);
    asm volatile("cp.async.commit_group;");

    for (int kt = 0; kt < 8; kt++) {
        if (kt < 7) asm volatile("cp.async.wait_group 1;");
        else        asm volatile("cp.async.wait_group 0;");
        __syncthreads();

        uint32_t stA = smem_base + ((kt % NSTAGE) * STG) * 2;
        uint32_t stB = stA + APLANE * 2;

#pragma unroll
        for (int ks = 0; ks < 4; ks++) {
            int kk = ks * 16;
            uint32_t a4[4][4];
#pragma unroll
            for (int mi = 0; mi < 4; mi++)
                ldsm4(a4[mi], stA + ((wm * 64 + mi * 16 + arow) * PSTR + kk + acol) * 2);
            uint32_t bf[4][2];
#pragma unroll
            for (int nip = 0; nip < 2; nip++) {
                uint32_t r[4];
                ldsm4t(r, stB + ((kk + arow) * PB_STR + wn * 32 + nip * 16 + acol) * 2);
                bf[2 * nip][0] = r[0]; bf[2 * nip][1] = r[1];
                bf[2 * nip + 1][0] = r[2]; bf[2 * nip + 1][1] = r[3];
            }
#pragma unroll
            for (int mi = 0; mi < 4; mi++)
#pragma unroll
                for (int ni = 0; ni < 4; ni++)
                    mmaf16(c[mi][ni], a4[mi], bf[ni]);
        }

        if (kt + 2 < 8) {
            issue(kt + 2);
            asm volatile("cp.async.commit_group;");
        }
    }

    // epilogue: bias + elu + 1, fp16 store (unroped), km atomics for k-group
    __half* dst = (grp ? g_kh : g_qh) + (size_t)b * DIMC * NPOS;
#pragma unroll
    for (int mi = 0; mi < 4; mi++) {
        int r0 = o0 + wm * 64 + mi * 16 + g4;
        int r1 = r0 + 8;
        float bias0 = __ldg(&qk_b[grp * DIMC + r0]);
        float bias1 = __ldg(&qk_b[grp * DIMC + r1]);
        float rs0 = 0.f, rs1 = 0.f;
#pragma unroll
        for (int ni = 0; ni < 4; ni++) {
            int p = p0 + wn * 32 + ni * 8 + tg * 2;
            float v00 = elu1(c[mi][ni][0] + bias0);
            float v01 = elu1(c[mi][ni][1] + bias0);
            float v10 = elu1(c[mi][ni][2] + bias1);
            float v11 = elu1(c[mi][ni][3] + bias1);
            *(uint32_t*)&dst[(size_t)r0 * NPOS + p] = packh(__float2half_rn(v00), __float2half_rn(v01));
            *(uint32_t*)&dst[(size_t)r1 * NPOS + p] = packh(__float2half_rn(v10), __float2half_rn(v11));
            rs0 += v00 + v01;
            rs1 += v10 + v11;
        }
        if (grp) {
            rs0 += __shfl_xor_sync(0xffffffffu, rs0, 1);
            rs0 += __shfl_xor_sync(0xffffffffu, rs0, 2);
            rs1 += __shfl_xor_sync(0xffffffffu, rs1, 1);
            rs1 += __shfl_xor_sync(0xffffffffu, rs1, 2);
            if (tg == 0) {
                atomicAdd(&g_km[b * DIMC + r0], rs0 * (1.f / NPOS));
                atomicAdd(&g_km[b * DIMC + r1], rs1 * (1.f / NPOS));
            }
        }
    }
}

// ---------------- kv kernel (n-split x8): rope k staging, fp16 V, 1 MMA ----------------
#define KV_STR 72

__global__ __launch_bounds__(256) void kv_kernel() {
    __shared__ __align__(16) __half sa[64 * KV_STR];      // rope(k) [d][n]
    __shared__ __align__(16) __half sb[64 * KV_STR];      // v fp16  [e][n]

    int tid = threadIdx.x;
    int lane = tid & 31, wid = tid >> 5;
    int wm = wid >> 2, wn = wid & 3;
    int g4 = lane >> 2, tg = lane & 3;
    int bh = blockIdx.x, chunk = blockIdx.y;
    int b = bh >> 4, h = bh & 15;
    size_t base = ((size_t)b * DIMC + h * HD) * NPOS;
    const __half* K = g_kh + base;
    const __half* V = g_xh + base;

    int kd2 = tid >> 3, kng = (tid & 7) * 8;
    int ve = tid >> 2, vng = (tid & 3) * 16;

    float c[2][2][4];
#pragma unroll
    for (int i = 0; i < 2; i++)
#pragma unroll
        for (int j = 0; j < 2; j++)
#pragma unroll
            for (int k = 0; k < 4; k++) c[i][j][k] = 0.f;

    for (int sub = 0; sub < 2; sub++) {
        int n0 = chunk * 128 + sub * 64;
        // stage rope(k): 8 n per thread
        {
            int r0 = 2 * kd2, r1 = r0 + 1;
            size_t o0 = (size_t)r0 * NPOS + n0 + kng;
            size_t o1 = o0 + NPOS;
            uint4 kh0 = *(const uint4*)&K[o0];
            uint4 kh1 = *(const uint4*)&K[o1];
            const __half* p0 = (const __half*)&kh0;
            const __half* p1 = (const __half*)&kh1;
            int j = h * 32 + kd2;
            const float* Cp = &g_cos[(size_t)j * NPOS + n0 + kng];
            const float* Sp = &g_sin[(size_t)j * NPOS + n0 + kng];
            float4 cA = *(const float4*)Cp, cB = *(const float4*)(Cp + 4);
            float4 sA = *(const float4*)Sp, sB = *(const float4*)(Sp + 4);
            float csv[8] = {cA.x, cA.y, cA.z, cA.w, cB.x, cB.y, cB.z, cB.w};
            float snv[8] = {sA.x, sA.y, sA.z, sA.w, sB.x, sB.y, sB.z, sB.w};
            __half oh0[8], oh1[8];
#pragma unroll
            for (int t = 0; t < 8; t++) {
                float k0 = __half2float(p0[t]);
                float k1 = __half2float(p1[t]);
                oh0[t] = __float2half_rn(csv[t] * k0 - snv[t] * k1);
                oh1[t] = __float2half_rn(snv[t] * k0 + csv[t] * k1);
            }
            *(uint4*)&sa[r0 * KV_STR + kng] = *(uint4*)oh0;
            *(uint4*)&sa[r1 * KV_STR + kng] = *(uint4*)oh1;
        }
        // stage v: straight fp16 vector copy, 16 n per thread
        {
            const __half* Vp = &V[(size_t)ve * NPOS + n0 + vng];
            *(uint4*)&sb[ve * KV_STR + vng] = *(const uint4*)Vp;
            *(uint4*)&sb[ve * KV_STR + vng + 8] = *(const uint4*)(Vp + 8);
        }
        __syncthreads();

#pragma unroll
        for (int ks = 0; ks < 4; ks++) {
            int kk = ks * 16;
            int col = kk + tg * 2;
            uint32_t ah[2][4];
#pragma unroll
            for (int mi = 0; mi < 2; mi++) {
                int d = wm * 32 + mi * 16 + g4;
                ah[mi][0] = *(uint32_t*)&sa[d * KV_STR + col];
                ah[mi][1] = *(uint32_t*)&sa[(d + 8) * KV_STR + col];
                ah[mi][2] = *(uint32_t*)&sa[d * KV_STR + col + 8];
                ah[mi][3] = *(uint32_t*)&sa[(d + 8) * KV_STR + col + 8];
            }
            uint32_t bv[2][2];
#pragma unroll
            for (int ni = 0; ni < 2; ni++) {
                int e = wn * 16 + ni * 8 + g4;
                bv[ni][0] = *(uint32_t*)&sb[e * KV_STR + col];
                bv[ni][1] = *(uint32_t*)&sb[e * KV_STR + col + 8];
            }
#pragma unroll
            for (int mi = 0; mi < 2; mi++)
#pragma unroll
                for (int ni = 0; ni < 2; ni++)
                    mmaf16(c[mi][ni], ah[mi], bv[ni]);
        }
        __syncthreads();
    }

    float* KV = g_kv + (size_t)bh * HD * HD;
#pragma unroll
    for (int mi = 0; mi < 2; mi++) {
#pragma unroll
        for (int ni = 0; ni < 2; ni++) {
            int d0 = wm * 32 + mi * 16 + g4, d1 = d0 + 8;
            int e0 = wn * 16 + ni * 8 + tg * 2, e1 = e0 + 1;
            atomicAdd(&KV[e0 * HD + d0], c[mi][ni][0] * (1.f / NPOS));
            atomicAdd(&KV[e1 * HD + d0], c[mi][ni][1] * (1.f / NPOS));
            atomicAdd(&KV[e0 * HD + d1], c[mi][ni][2] * (1.f / NPOS));
            atomicAdd(&KV[e1 * HD + d1], c[mi][ni][3] * (1.f / NPOS));
        }
    }
}

// ---------------- out kernel: 512 threads, attn + fused lepe (fp16 halo) ----------------
#define OA_STR 66
#define OB_STR 72
#define OSMEM_BYTES ((128 * OA_STR + 2 * 64 * OB_STR) * 2 + (128 + 576 + 64 + 64 * 198) * 4)

__global__ __launch_bounds__(512, 2) void out_kernel(float* __restrict__ out,
                                                     const float* __restrict__ lepe_w,
                                                     const float* __restrict__ lepe_b) {
    extern __shared__ __align__(16) char sm_raw[];
    __half* sa = (__half*)sm_raw;              // roped q [n][d] 128 x OA_STR
    __half* skh = sa + 128 * OA_STR;
    __half* skl = skh + 64 * OB_STR;
    float* s_z = (float*)(skl + 64 * OB_STR);
    float* sw = s_z + 128;
    float* sbias = sw + 576;
    float* sx = sbias + 64;

    int tid = threadIdx.x;
    int lane = tid & 31, wid = tid >> 5;
    int wm = wid >> 2, wn = wid & 3;           // 4 n-groups x 4 e-groups
    int g4 = lane >> 2, tg = lane & 3;

    int nt = blockIdx.x, bh = blockIdx.y;
    int b = bh >> 4, h = bh & 15;
    int n0 = nt * 128;
    int y0 = nt * 4;
    size_t qbase = ((size_t)b * DIMC + h * HD) * NPOS;
    const __half* Q = g_qh + qbase;
    const __half* Xh = g_xh + qbase;
    const float* km = g_km + b * DIMC + h * HD;

    if (tid < 128) s_z[tid] = 0.f;
    // stage kv hi/lo
    {
        const float* KV = g_kv + (size_t)bh * HD * HD;
        for (int i = tid; i < 4096; i += 512) {
            int e = i >> 6, d = i & 63;
            __half hi, lo;
            splith(KV[i], hi, lo);
            skh[e * OB_STR + d] = hi;
            skl[e * OB_STR + d] = lo;
        }
    }
    // stage lepe weights/bias
    for (int i = tid; i < 576; i += 512) sw[i] = __ldg(&lepe_w[h * 576 + i]);
    if (tid < 64) sbias[tid] = __ldg(&lepe_b[h * 64 + tid]);
    // stage x halo rows from fp16 plane
    {
#pragma unroll
        for (int rr = 0; rr < 6; rr++) {
            int yy = y0 - 1 + rr;
            bool valid = (yy >= 0) && (yy < 32);
            if (tid < 256) {
                int e = tid >> 2, q8 = (tid & 3) * 8;
                float vf[8];
                if (valid) {
                    uint4 v = *(const uint4*)&Xh[(size_t)e * 1024 + yy * 32 + q8];
                    const __half* ph = (const __half*)&v;
#pragma unroll
                    for (int t = 0; t < 8; t++) vf[t] = __half2float(ph[t]);
                } else {
#pragma unroll
                    for (int t = 0; t < 8; t++) vf[t] = 0.f;
                }
                float* d = &sx[e * 198 + rr * 33 + q8];
#pragma unroll
                for (int t = 0; t < 8; t++) d[t] = vf[t];
            }
        }
    }
    __syncthreads();

    // stage rope(q) + z partial: 4 thread-quarters cover d2 0..31 over 8 passes
    float zacc = 0.f;
    int nfix = tid & 127;
    int quarter = tid >> 7;
#pragma unroll 4
    for (int pass = 0; pass < 8; pass++) {
        int d2 = quarter + pass * 4;
        size_t i0 = (size_t)(2 * d2) * NPOS + n0 + nfix;
        size_t i1 = i0 + NPOS;
        float q0 = __half2float(Q[i0]);
        float q1 = __half2float(Q[i1]);
        float km0 = __ldg(&km[2 * d2]);
        float km1 = __ldg(&km[2 * d2 + 1]);
        zacc += q0 * km0 + q1 * km1;
        int j = h * 32 + d2;
        float cs = g_cos[(size_t)j * NPOS + n0 + nfix];
        float sn = g_sin[(size_t)j * NPOS + n0 + nfix];
        float r0 = cs * q0 - sn * q1;
        float r1 = sn * q0 + cs * q1;
        *(uint32_t*)&sa[nfix * OA_STR + 2 * d2] = packh(__float2half_rn(r0), __float2half_rn(r1));
    }
    atomicAdd(&s_z[nfix], zacc);
    __syncthreads();

    float c[2][2][4];
#pragma unroll
    for (int i = 0; i < 2; i++)
#pragma unroll
        for (int j = 0; j < 2; j++)
#pragma unroll
            for (int k = 0; k < 4; k++) c[i][j][k] = 0.f;

#pragma unroll
    for (int ks = 0; ks < 4; ks++) {
        int kk = ks * 16;
        int col = kk + tg * 2;
        uint32_t ah[2][4];
#pragma unroll
        for (int mi = 0; mi < 2; mi++) {
            int n = wm * 32 + mi * 16 + g4;
            ah[mi][0] = *(uint32_t*)&sa[n * OA_STR + col];
            ah[mi][1] = *(uint32_t*)&sa[(n + 8) * OA_STR + col];
            ah[mi][2] = *(uint32_t*)&sa[n * OA_STR + col + 8];
            ah[mi][3] = *(uint32_t*)&sa[(n + 8) * OA_STR + col + 8];
        }
        uint32_t bh2[2][2], bl2[2][2];
#pragma unroll
        for (int ni = 0; ni < 2; ni++) {
            int e = wn * 16 + ni * 8 + g4;
            bh2[ni][0] = *(uint32_t*)&skh[e * OB_STR + col];
            bh2[ni][1] = *(uint32_t*)&skh[e * OB_STR + col + 8];
            bl2[ni][0] = *(uint32_t*)&skl[e * OB_STR + col];
            bl2[ni][1] = *(uint32_t*)&skl[e * OB_STR + col + 8];
        }
#pragma unroll
        for (int mi = 0; mi < 2; mi++)
#pragma unroll
            for (int ni = 0; ni < 2; ni++) {
                mmaf16(c[mi][ni], ah[mi], bh2[ni]);
                mmaf16(c[mi][ni], ah[mi], bl2[ni]);
            }
    }

    // epilogue: z scale + fused lepe stencil
    float* O = out + qbase;
#pragma unroll
    for (int ni = 0; ni < 2; ni++) {
        int e0 = wn * 16 + ni * 8 + tg * 2;
        int e1 = e0 + 1;
        float b0 = sbias[e0], b1 = sbias[e1];

        auto lepe_at = [&](int e, float bs, int nr) -> float {
            int yloc = nr >> 5, xx = nr & 31;
            const float* base = &sx[e * 198 + yloc * 33];
            const float* wv = &sw[e * 9];
            float acc = bs;
#pragma unroll
            for (int i = 0; i < 3; i++) {
                const float* rw = base + i * 33;
                acc += wv[i * 3 + 1] * rw[xx];
                if (xx > 0)  acc += wv[i * 3 + 0] * rw[xx - 1];
                if (xx < 31) acc += wv[i * 3 + 2] * rw[xx + 1];
            }
            return acc;
        };

#pragma unroll
        for (int mi = 0; mi < 2; mi++) {
            int nr0 = wm * 32 + mi * 16 + g4;
            int nr1 = nr0 + 8;
            float z0 = 1.f / (s_z[nr0] + 1e-6f);
            float z1 = 1.f / (s_z[nr1] + 1e-6f);
            size_t i00 = (size_t)e0 * NPOS + n0 + nr0;
            size_t i01 = (size_t)e1 * NPOS + n0 + nr0;
            size_t i10 = (size_t)e0 * NPOS + n0 + nr1;
            size_t i11 = (size_t)e1 * NPOS + n0 + nr1;
            O[i00] = c[mi][ni][0] * z0 + lepe_at(e0, b0, nr0);
            O[i01] = c[mi][ni][1] * z0 + lepe_at(e1, b1, nr0);
            O[i10] = c[mi][ni][2] * z1 + lepe_at(e0, b0, nr1);
            O[i11] = c[mi][ni][3] * z1 + lepe_at(e1, b1, nr1);
        }
    }
}

// ---------------- launch ----------------
extern "C" void kernel_launch(void* const* d_in, const int* in_sizes, int n_in,
                              void* d_out, int out_size) {
    const float* x      = (const float*)d_in[0];
    const float* qk_w   = (const float*)d_in[1];
    const float* qk_b   = (const float*)d_in[2];
    const float* lepe_w = (const float*)d_in[3];
    const float* lepe_b = (const float*)d_in[4];
    float* out = (float*)d_out;

    cudaFuncSetAttribute(proj_kernel, cudaFuncAttributeMaxDynamicSharedMemorySize, PROJ_SMEM);
    cudaFuncSetAttribute(out_kernel, cudaFuncAttributeMaxDynamicSharedMemorySize, OSMEM_BYTES);

    // proj kept as 4th launch (ncu capture slot)
    prep_misc_kernel<<<(BATCHN * NH * HD * HD + 255) / 256, 256>>>();
    prep_w_kernel<<<2 * DIMC * KPROJ / 256, 256>>>(qk_w);
    xhalf_kernel<<<BATCHN * DIMC * NPOS / 8 / 256, 256>>>(x);
    proj_kernel<<<dim3(8, 8, 2 * BATCHN), 256, PROJ_SMEM>>>(qk_b);
    kv_kernel<<<dim3(BATCHN * NH, 8), 256>>>();
    out_kernel<<<dim3(8, BATCHN * NH), 512, OSMEM_BYTES>>>(out, lepe_w, lepe_b);
}

// round 15
// speedup vs baseline: 1.1677x; 1.0156x over previous
#include <cuda_runtime.h>
#include <cuda_fp16.h>
#include <cstdint>
#include <math.h>

#define DIMC 1024
#define NH   16
#define HD   64
#define NPOS 1024
#define BATCHN 16
#define KPROJ 512

// ---------------- scratch ----------------
__device__ __half g_wf16[2 * DIMC * KPROJ];                 // W rounded fp16
__device__ __half g_xh[BATCHN * DIMC * NPOS];               // x fp16, native [b][c][p]
__device__ __half g_qh[BATCHN * DIMC * NPOS];               // unroped q fp16 [b][o][p]
__device__ __half g_kh[BATCHN * DIMC * NPOS];               // unroped k
__device__ float g_km[BATCHN * DIMC];
__device__ float g_kv[BATCHN * NH * HD * HD];               // [bh][e][d] fp32 accum
__device__ float g_cos[(DIMC / 2) * NPOS];                  // [j][p]
__device__ float g_sin[(DIMC / 2) * NPOS];

// ---------------- helpers ----------------
__device__ __forceinline__ void mmaf16(float c[4], const uint32_t a[4], const uint32_t b[2]) {
    asm volatile(
        "mma.sync.aligned.m16n8k16.row.col.f32.f16.f16.f32 "
        "{%0,%1,%2,%3}, {%4,%5,%6,%7}, {%8,%9}, {%0,%1,%2,%3};"
        : "+f"(c[0]), "+f"(c[1]), "+f"(c[2]), "+f"(c[3])
        : "r"(a[0]), "r"(a[1]), "r"(a[2]), "r"(a[3]), "r"(b[0]), "r"(b[1]));
}

__device__ __forceinline__ void splith(float v, __half& hi, __half& lo) {
    hi = __float2half_rn(v);
    lo = __float2half_rn(v - __half2float(hi));
}

__device__ __forceinline__ uint32_t packh(__half a, __half b) {
    return (uint32_t)__half_as_ushort(a) | ((uint32_t)__half_as_ushort(b) << 16);
}

__device__ __forceinline__ float elu1(float v) { return v > 0.f ? v + 1.f : expf(v); }

__device__ __forceinline__ uint32_t cvta_sm(const void* p) {
    return (uint32_t)__cvta_generic_to_shared(p);
}

__device__ __forceinline__ void cp16(uint32_t saddr, const void* g) {
    asm volatile("cp.async.cg.shared.global [%0], [%1], 16;" :: "r"(saddr), "l"(g));
}

__device__ __forceinline__ void ldsm4(uint32_t r[4], uint32_t addr) {
    asm volatile("ldmatrix.sync.aligned.m8n8.x4.shared.b16 {%0,%1,%2,%3}, [%4];"
                 : "=r"(r[0]), "=r"(r[1]), "=r"(r[2]), "=r"(r[3]) : "r"(addr));
}

__device__ __forceinline__ void ldsm4t(uint32_t r[4], uint32_t addr) {
    asm volatile("ldmatrix.sync.aligned.m8n8.x4.trans.shared.b16 {%0,%1,%2,%3}, [%4];"
                 : "=r"(r[0]), "=r"(r[1]), "=r"(r[2]), "=r"(r[3]) : "r"(addr));
}

// ---------------- fused prep: xhalf + tables + W convert + zeroing ----------------
__global__ __launch_bounds__(256) void prep_all_kernel(const float* __restrict__ x,
                                                       const float* __restrict__ qk_w) {
    int idx = blockIdx.x * 256 + threadIdx.x;   // 0 .. 2M-1
    // x fp32 -> fp16 (8 elements per thread)
    {
        size_t i = (size_t)idx;
        const float4* X4 = (const float4*)x;
        float4 a = X4[2 * i], b = X4[2 * i + 1];
        uint4 o;
        o.x = packh(__float2half_rn(a.x), __float2half_rn(a.y));
        o.y = packh(__float2half_rn(a.z), __float2half_rn(a.w));
        o.z = packh(__float2half_rn(b.x), __float2half_rn(b.y));
        o.w = packh(__float2half_rn(b.z), __float2half_rn(b.w));
        ((uint4*)g_xh)[i] = o;
    }
    // rope tables
    if (idx < (DIMC / 2) * NPOS) {
        int j = idx >> 10, p = idx & (NPOS - 1);
        int jj = (j < 256) ? j : j - 256;
        float pos = (float)((j < 256) ? (p >> 5) : (p & 31));
        float theta = expf(-(float)jj * (9.210340371976184f / 256.f));
        float s, c;
        sincosf(pos * theta, &s, &c);
        g_cos[idx] = c;
        g_sin[idx] = s;
    }
    // W fp16
    if (idx < 2 * DIMC * KPROJ) g_wf16[idx] = __float2half_rn(qk_w[idx]);
    // zero accumulators
    if (idx < BATCHN * NH * HD * HD) g_kv[idx] = 0.f;
    if (idx < BATCHN * DIMC) g_km[idx] = 0.f;
}

// ---------------- projection GEMM: fp16, KCHUNK=64, 3-stage ring ----------------
#define PSTR 72
#define PB_STR 136
#define APLANE (128 * PSTR)                  // 9216
#define BPLANE (64 * PB_STR)                 // 8704
#define STG (APLANE + BPLANE)                // 17920 halves
#define NSTAGE 3
#define PROJ_SMEM (NSTAGE * STG * 2)         // 107520 bytes

__global__ __launch_bounds__(256) void proj_kernel(const float* __restrict__ qk_b) {
    extern __shared__ __align__(16) __half sm[];

    int tid = threadIdx.x;
    int lane = tid & 31, wid = tid >> 5;
    int wm = wid >> 2, wn = wid & 3;
    int g4 = lane >> 2, tg = lane & 3;
    int arow = (lane & 7) + ((lane >> 3) & 1) * 8;
    int acol = (lane >> 4) * 8;

    int pt = blockIdx.x, ot = blockIdx.y;
    int b = blockIdx.z >> 1, grp = blockIdx.z & 1;
    const __half* W = g_wf16 + (size_t)grp * DIMC * KPROJ;
    const __half* Xc = g_xh + ((size_t)b * DIMC + grp * KPROJ) * NPOS;
    int o0 = ot * 128, p0 = pt * 128;

    float c[4][4][4];
#pragma unroll
    for (int i = 0; i < 4; i++)
#pragma unroll
        for (int j = 0; j < 4; j++)
#pragma unroll
            for (int k = 0; k < 4; k++) c[i][j][k] = 0.f;

    uint32_t smem_base = cvta_sm(sm);

    auto issue = [&](int kt) {
        uint32_t st = smem_base + ((kt % NSTAGE) * STG) * 2;
        int c0 = kt * 64;
#pragma unroll
        for (int t = 0; t < 4; t++) {
            int i = tid + t * 256;
            int row = i >> 3, cs = (i & 7) * 8;
            cp16(st + (row * PSTR + cs) * 2, W + (size_t)(o0 + row) * KPROJ + c0 + cs);
        }
#pragma unroll
        for (int t = 0; t < 4; t++) {
            int i = tid + t * 256;
            int row = i >> 4, ch = (i & 15) * 8;
            cp16(st + (APLANE + row * PB_STR + ch) * 2,
                 Xc + (size_t)(c0 + row) * NPOS + p0 + ch);
        }
    };

    issue(0);
    asm volatile("cp.async.commit_group;");
    issue(1);
    asm volatile("cp.async.commit_group;");

    for (int kt = 0; kt < 8; kt++) {
        if (kt < 7) asm volatile("cp.async.wait_group 1;");
        else        asm volatile("cp.async.wait_group 0;");
        __syncthreads();

        uint32_t stA = smem_base + ((kt % NSTAGE) * STG) * 2;
        uint32_t stB = stA + APLANE * 2;

#pragma unroll
        for (int ks = 0; ks < 4; ks++) {
            int kk = ks * 16;
            uint32_t a4[4][4];
#pragma unroll
            for (int mi = 0; mi < 4; mi++)
                ldsm4(a4[mi], stA + ((wm * 64 + mi * 16 + arow) * PSTR + kk + acol) * 2);
            uint32_t bf[4][2];
#pragma unroll
            for (int nip = 0; nip < 2; nip++) {
                uint32_t r[4];
                ldsm4t(r, stB + ((kk + arow) * PB_STR + wn * 32 + nip * 16 + acol) * 2);
                bf[2 * nip][0] = r[0]; bf[2 * nip][1] = r[1];
                bf[2 * nip + 1][0] = r[2]; bf[2 * nip + 1][1] = r[3];
            }
#pragma unroll
            for (int mi = 0; mi < 4; mi++)
#pragma unroll
                for (int ni = 0; ni < 4; ni++)
                    mmaf16(c[mi][ni], a4[mi], bf[ni]);
        }

        if (kt + 2 < 8) {
            issue(kt + 2);
            asm volatile("cp.async.commit_group;");
        }
    }

    // epilogue: bias + elu + 1, fp16 store (unroped), km atomics for k-group
    __half* dst = (grp ? g_kh : g_qh) + (size_t)b * DIMC * NPOS;
#pragma unroll
    for (int mi = 0; mi < 4; mi++) {
        int r0 = o0 + wm * 64 + mi * 16 + g4;
        int r1 = r0 + 8;
        float bias0 = __ldg(&qk_b[grp * DIMC + r0]);
        float bias1 = __ldg(&qk_b[grp * DIMC + r1]);
        float rs0 = 0.f, rs1 = 0.f;
#pragma unroll
        for (int ni = 0; ni < 4; ni++) {
            int p = p0 + wn * 32 + ni * 8 + tg * 2;
            float v00 = elu1(c[mi][ni][0] + bias0);
            float v01 = elu1(c[mi][ni][1] + bias0);
            float v10 = elu1(c[mi][ni][2] + bias1);
            float v11 = elu1(c[mi][ni][3] + bias1);
            *(uint32_t*)&dst[(size_t)r0 * NPOS + p] = packh(__float2half_rn(v00), __float2half_rn(v01));
            *(uint32_t*)&dst[(size_t)r1 * NPOS + p] = packh(__float2half_rn(v10), __float2half_rn(v11));
            rs0 += v00 + v01;
            rs1 += v10 + v11;
        }
        if (grp) {
            rs0 += __shfl_xor_sync(0xffffffffu, rs0, 1);
            rs0 += __shfl_xor_sync(0xffffffffu, rs0, 2);
            rs1 += __shfl_xor_sync(0xffffffffu, rs1, 1);
            rs1 += __shfl_xor_sync(0xffffffffu, rs1, 2);
            if (tg == 0) {
                atomicAdd(&g_km[b * DIMC + r0], rs0 * (1.f / NPOS));
                atomicAdd(&g_km[b * DIMC + r1], rs1 * (1.f / NPOS));
            }
        }
    }
}

// ---------------- kv kernel (n-split x8): rope k staging, fp16 V, 1 MMA ----------------
#define KV_STR 72

__global__ __launch_bounds__(256) void kv_kernel() {
    __shared__ __align__(16) __half sa[64 * KV_STR];      // rope(k) [d][n]
    __shared__ __align__(16) __half sb[64 * KV_STR];      // v fp16  [e][n]

    int tid = threadIdx.x;
    int lane = tid & 31, wid = tid >> 5;
    int wm = wid >> 2, wn = wid & 3;
    int g4 = lane >> 2, tg = lane & 3;
    int bh = blockIdx.x, chunk = blockIdx.y;
    int b = bh >> 4, h = bh & 15;
    size_t base = ((size_t)b * DIMC + h * HD) * NPOS;
    const __half* K = g_kh + base;
    const __half* V = g_xh + base;

    int kd2 = tid >> 3, kng = (tid & 7) * 8;
    int ve = tid >> 2, vng = (tid & 3) * 16;

    float c[2][2][4];
#pragma unroll
    for (int i = 0; i < 2; i++)
#pragma unroll
        for (int j = 0; j < 2; j++)
#pragma unroll
            for (int k = 0; k < 4; k++) c[i][j][k] = 0.f;

    for (int sub = 0; sub < 2; sub++) {
        int n0 = chunk * 128 + sub * 64;
        // stage rope(k): 8 n per thread
        {
            int r0 = 2 * kd2, r1 = r0 + 1;
            size_t o0 = (size_t)r0 * NPOS + n0 + kng;
            size_t o1 = o0 + NPOS;
            uint4 kh0 = *(const uint4*)&K[o0];
            uint4 kh1 = *(const uint4*)&K[o1];
            const __half* p0 = (const __half*)&kh0;
            const __half* p1 = (const __half*)&kh1;
            int j = h * 32 + kd2;
            const float* Cp = &g_cos[(size_t)j * NPOS + n0 + kng];
            const float* Sp = &g_sin[(size_t)j * NPOS + n0 + kng];
            float4 cA = *(const float4*)Cp, cB = *(const float4*)(Cp + 4);
            float4 sA = *(const float4*)Sp, sB = *(const float4*)(Sp + 4);
            float csv[8] = {cA.x, cA.y, cA.z, cA.w, cB.x, cB.y, cB.z, cB.w};
            float snv[8] = {sA.x, sA.y, sA.z, sA.w, sB.x, sB.y, sB.z, sB.w};
            __half oh0[8], oh1[8];
#pragma unroll
            for (int t = 0; t < 8; t++) {
                float k0 = __half2float(p0[t]);
                float k1 = __half2float(p1[t]);
                oh0[t] = __float2half_rn(csv[t] * k0 - snv[t] * k1);
                oh1[t] = __float2half_rn(snv[t] * k0 + csv[t] * k1);
            }
            *(uint4*)&sa[r0 * KV_STR + kng] = *(uint4*)oh0;
            *(uint4*)&sa[r1 * KV_STR + kng] = *(uint4*)oh1;
        }
        // stage v: straight fp16 vector copy
        {
            const __half* Vp = &V[(size_t)ve * NPOS + n0 + vng];
            *(uint4*)&sb[ve * KV_STR + vng] = *(const uint4*)Vp;
            *(uint4*)&sb[ve * KV_STR + vng + 8] = *(const uint4*)(Vp + 8);
        }
        __syncthreads();

#pragma unroll
        for (int ks = 0; ks < 4; ks++) {
            int kk = ks * 16;
            int col = kk + tg * 2;
            uint32_t ah[2][4];
#pragma unroll
            for (int mi = 0; mi < 2; mi++) {
                int d = wm * 32 + mi * 16 + g4;
                ah[mi][0] = *(uint32_t*)&sa[d * KV_STR + col];
                ah[mi][1] = *(uint32_t*)&sa[(d + 8) * KV_STR + col];
                ah[mi][2] = *(uint32_t*)&sa[d * KV_STR + col + 8];
                ah[mi][3] = *(uint32_t*)&sa[(d + 8) * KV_STR + col + 8];
            }
            uint32_t bv[2][2];
#pragma unroll
            for (int ni = 0; ni < 2; ni++) {
                int e = wn * 16 + ni * 8 + g4;
                bv[ni][0] = *(uint32_t*)&sb[e * KV_STR + col];
                bv[ni][1] = *(uint32_t*)&sb[e * KV_STR + col + 8];
            }
#pragma unroll
            for (int mi = 0; mi < 2; mi++)
#pragma unroll
                for (int ni = 0; ni < 2; ni++)
                    mmaf16(c[mi][ni], ah[mi], bv[ni]);
        }
        __syncthreads();
    }

    float* KV = g_kv + (size_t)bh * HD * HD;
#pragma unroll
    for (int mi = 0; mi < 2; mi++) {
#pragma unroll
        for (int ni = 0; ni < 2; ni++) {
            int d0 = wm * 32 + mi * 16 + g4, d1 = d0 + 8;
            int e0 = wn * 16 + ni * 8 + tg * 2, e1 = e0 + 1;
            atomicAdd(&KV[e0 * HD + d0], c[mi][ni][0] * (1.f / NPOS));
            atomicAdd(&KV[e1 * HD + d0], c[mi][ni][1] * (1.f / NPOS));
            atomicAdd(&KV[e0 * HD + d1], c[mi][ni][2] * (1.f / NPOS));
            atomicAdd(&KV[e1 * HD + d1], c[mi][ni][3] * (1.f / NPOS));
        }
    }
}

// ---------------- out kernel: 512 threads, attn + fused lepe (fp16 halo) ----------------
#define OA_STR 66
#define OB_STR 72
#define OSMEM_BYTES ((128 * OA_STR + 2 * 64 * OB_STR) * 2 + (128 + 576 + 64 + 64 * 198) * 4)

__global__ __launch_bounds__(512, 2) void out_kernel(float* __restrict__ out,
                                                     const float* __restrict__ lepe_w,
                                                     const float* __restrict__ lepe_b) {
    extern __shared__ __align__(16) char sm_raw[];
    __half* sa = (__half*)sm_raw;              // roped q [n][d] 128 x OA_STR
    __half* skh = sa + 128 * OA_STR;
    __half* skl = skh + 64 * OB_STR;
    float* s_z = (float*)(skl + 64 * OB_STR);
    float* sw = s_z + 128;
    float* sbias = sw + 576;
    float* sx = sbias + 64;

    int tid = threadIdx.x;
    int lane = tid & 31, wid = tid >> 5;
    int wm = wid >> 2, wn = wid & 3;           // 4 n-groups x 4 e-groups
    int g4 = lane >> 2, tg = lane & 3;

    int nt = blockIdx.x, bh = blockIdx.y;
    int b = bh >> 4, h = bh & 15;
    int n0 = nt * 128;
    int y0 = nt * 4;
    size_t qbase = ((size_t)b * DIMC + h * HD) * NPOS;
    const __half* Q = g_qh + qbase;
    const __half* Xh = g_xh + qbase;
    const float* km = g_km + b * DIMC + h * HD;

    if (tid < 128) s_z[tid] = 0.f;
    // stage kv hi/lo
    {
        const float* KV = g_kv + (size_t)bh * HD * HD;
        for (int i = tid; i < 4096; i += 512) {
            int e = i >> 6, d = i & 63;
            __half hi, lo;
            splith(KV[i], hi, lo);
            skh[e * OB_STR + d] = hi;
            skl[e * OB_STR + d] = lo;
        }
    }
    // stage lepe weights/bias
    for (int i = tid; i < 576; i += 512) sw[i] = __ldg(&lepe_w[h * 576 + i]);
    if (tid < 64) sbias[tid] = __ldg(&lepe_b[h * 64 + tid]);
    // stage x halo rows from fp16 plane: 64ch x 6 rows x 32 = 1536 uint4-groups of 8 halves
    {
        for (int i = tid; i < 1536; i += 512) {
            int e = i / 24;                     // 24 groups of 8 per channel (6 rows x 4)
            int rem = i - e * 24;
            int rr = rem >> 2, q8 = (rem & 3) * 8;
            int yy = y0 - 1 + rr;
            float vf[8];
            if (yy >= 0 && yy < 32) {
                uint4 v = *(const uint4*)&Xh[(size_t)e * 1024 + yy * 32 + q8];
                const __half* ph = (const __half*)&v;
#pragma unroll
                for (int t = 0; t < 8; t++) vf[t] = __half2float(ph[t]);
            } else {
#pragma unroll
                for (int t = 0; t < 8; t++) vf[t] = 0.f;
            }
            float* d = &sx[e * 198 + rr * 33 + q8];
#pragma unroll
            for (int t = 0; t < 8; t++) d[t] = vf[t];
        }
    }
    __syncthreads();

    // stage rope(q) + z partial
    float zacc = 0.f;
    int nfix = tid & 127;
    int quarter = tid >> 7;
#pragma unroll 4
    for (int pass = 0; pass < 8; pass++) {
        int d2 = quarter + pass * 4;
        size_t i0 = (size_t)(2 * d2) * NPOS + n0 + nfix;
        size_t i1 = i0 + NPOS;
        float q0 = __half2float(Q[i0]);
        float q1 = __half2float(Q[i1]);
        float km0 = __ldg(&km[2 * d2]);
        float km1 = __ldg(&km[2 * d2 + 1]);
        zacc += q0 * km0 + q1 * km1;
        int j = h * 32 + d2;
        float cs = g_cos[(size_t)j * NPOS + n0 + nfix];
        float sn = g_sin[(size_t)j * NPOS + n0 + nfix];
        float r0 = cs * q0 - sn * q1;
        float r1 = sn * q0 + cs * q1;
        *(uint32_t*)&sa[nfix * OA_STR + 2 * d2] = packh(__float2half_rn(r0), __float2half_rn(r1));
    }
    atomicAdd(&s_z[nfix], zacc);
    __syncthreads();

    float c[2][2][4];
#pragma unroll
    for (int i = 0; i < 2; i++)
#pragma unroll
        for (int j = 0; j < 2; j++)
#pragma unroll
            for (int k = 0; k < 4; k++) c[i][j][k] = 0.f;

#pragma unroll
    for (int ks = 0; ks < 4; ks++) {
        int kk = ks * 16;
        int col = kk + tg * 2;
        uint32_t ah[2][4];
#pragma unroll
        for (int mi = 0; mi < 2; mi++) {
            int n = wm * 32 + mi * 16 + g4;
            ah[mi][0] = *(uint32_t*)&sa[n * OA_STR + col];
            ah[mi][1] = *(uint32_t*)&sa[(n + 8) * OA_STR + col];
            ah[mi][2] = *(uint32_t*)&sa[n * OA_STR + col + 8];
            ah[mi][3] = *(uint32_t*)&sa[(n + 8) * OA_STR + col + 8];
        }
        uint32_t bh2[2][2], bl2[2][2];
#pragma unroll
        for (int ni = 0; ni < 2; ni++) {
            int e = wn * 16 + ni * 8 + g4;
            bh2[ni][0] = *(uint32_t*)&skh[e * OB_STR + col];
            bh2[ni][1] = *(uint32_t*)&skh[e * OB_STR + col + 8];
            bl2[ni][0] = *(uint32_t*)&skl[e * OB_STR + col];
            bl2[ni][1] = *(uint32_t*)&skl[e * OB_STR + col + 8];
        }
#pragma unroll
        for (int mi = 0; mi < 2; mi++)
#pragma unroll
            for (int ni = 0; ni < 2; ni++) {
                mmaf16(c[mi][ni], ah[mi], bh2[ni]);
                mmaf16(c[mi][ni], ah[mi], bl2[ni]);
            }
    }

    // epilogue: z scale + fused lepe stencil
    float* O = out + qbase;
#pragma unroll
    for (int ni = 0; ni < 2; ni++) {
        int e0 = wn * 16 + ni * 8 + tg * 2;
        int e1 = e0 + 1;
        float b0 = sbias[e0], b1 = sbias[e1];

        auto lepe_at = [&](int e, float bs, int nr) -> float {
            int yloc = nr >> 5, xx = nr & 31;
            const float* base = &sx[e * 198 + yloc * 33];
            const float* wv = &sw[e * 9];
            float acc = bs;
#pragma unroll
            for (int i = 0; i < 3; i++) {
                const float* rw = base + i * 33;
                acc += wv[i * 3 + 1] * rw[xx];
                if (xx > 0)  acc += wv[i * 3 + 0] * rw[xx - 1];
                if (xx < 31) acc += wv[i * 3 + 2] * rw[xx + 1];
            }
            return acc;
        };

#pragma unroll
        for (int mi = 0; mi < 2; mi++) {
            int nr0 = wm * 32 + mi * 16 + g4;
            int nr1 = nr0 + 8;
            float z0 = 1.f / (s_z[nr0] + 1e-6f);
            float z1 = 1.f / (s_z[nr1] + 1e-6f);
            size_t i00 = (size_t)e0 * NPOS + n0 + nr0;
            size_t i01 = (size_t)e1 * NPOS + n0 + nr0;
            size_t i10 = (size_t)e0 * NPOS + n0 + nr1;
            size_t i11 = (size_t)e1 * NPOS + n0 + nr1;
            O[i00] = c[mi][ni][0] * z0 + lepe_at(e0, b0, nr0);
            O[i01] = c[mi][ni][1] * z0 + lepe_at(e1, b1, nr0);
            O[i10] = c[mi][ni][2] * z1 + lepe_at(e0, b0, nr1);
            O[i11] = c[mi][ni][3] * z1 + lepe_at(e1, b1, nr1);
        }
    }
}

// ---------------- launch ----------------
extern "C" void kernel_launch(void* const* d_in, const int* in_sizes, int n_in,
                              void* d_out, int out_size) {
    const float* x      = (const float*)d_in[0];
    const float* qk_w   = (const float*)d_in[1];
    const float* qk_b   = (const float*)d_in[2];
    const float* lepe_w = (const float*)d_in[3];
    const float* lepe_b = (const float*)d_in[4];
    float* out = (float*)d_out;

    cudaFuncSetAttribute(proj_kernel, cudaFuncAttributeMaxDynamicSharedMemorySize, PROJ_SMEM);
    cudaFuncSetAttribute(out_kernel, cudaFuncAttributeMaxDynamicSharedMemorySize, OSMEM_BYTES);

    // launches: prep(1) proj(2) kv(3) out(4) -> ncu capture slot = out
    prep_all_kernel<<<BATCHN * DIMC * NPOS / 8 / 256, 256>>>(x, qk_w);
    proj_kernel<<<dim3(8, 8, 2 * BATCHN), 256, PROJ_SMEM>>>(qk_b);
    kv_kernel<<<dim3(BATCHN * NH, 8), 256>>>();
    out_kernel<<<dim3(8, BATCHN * NH), 512, OSMEM_BYTES>>>(out, lepe_w, lepe_b);
}

// round 16
// speedup vs baseline: 1.2391x; 1.0611x over previous
#include <cuda_runtime.h>
#include <cuda_fp16.h>
#include <cstdint>
#include <math.h>

#define DIMC 1024
#define NH   16
#define HD   64
#define NPOS 1024
#define BATCHN 16
#define KPROJ 512

// ---------------- scratch ----------------
__device__ __half g_wf16[2 * DIMC * KPROJ];                 // W rounded fp16
__device__ __half g_xh[BATCHN * DIMC * NPOS];               // x fp16, native [b][c][p]
__device__ __half g_qh[BATCHN * DIMC * NPOS];               // unroped q fp16 [b][o][p]
__device__ __half g_kh[BATCHN * DIMC * NPOS];               // unroped k
__device__ float g_km[BATCHN * DIMC];
__device__ float g_kv[BATCHN * NH * HD * HD];               // [bh][e][d] fp32 accum
__device__ float g_cos[(DIMC / 2) * NPOS];                  // [j][p]
__device__ float g_sin[(DIMC / 2) * NPOS];

// ---------------- helpers ----------------
__device__ __forceinline__ void mmaf16(float c[4], const uint32_t a[4], const uint32_t b[2]) {
    asm volatile(
        "mma.sync.aligned.m16n8k16.row.col.f32.f16.f16.f32 "
        "{%0,%1,%2,%3}, {%4,%5,%6,%7}, {%8,%9}, {%0,%1,%2,%3};"
        : "+f"(c[0]), "+f"(c[1]), "+f"(c[2]), "+f"(c[3])
        : "r"(a[0]), "r"(a[1]), "r"(a[2]), "r"(a[3]), "r"(b[0]), "r"(b[1]));
}

__device__ __forceinline__ void splith(float v, __half& hi, __half& lo) {
    hi = __float2half_rn(v);
    lo = __float2half_rn(v - __half2float(hi));
}

__device__ __forceinline__ uint32_t packh(__half a, __half b) {
    return (uint32_t)__half_as_ushort(a) | ((uint32_t)__half_as_ushort(b) << 16);
}

__device__ __forceinline__ float elu1(float v) { return v > 0.f ? v + 1.f : expf(v); }

__device__ __forceinline__ uint32_t cvta_sm(const void* p) {
    return (uint32_t)__cvta_generic_to_shared(p);
}

__device__ __forceinline__ void cp16(uint32_t saddr, const void* g) {
    asm volatile("cp.async.cg.shared.global [%0], [%1], 16;" :: "r"(saddr), "l"(g));
}

__device__ __forceinline__ void ldsm4(uint32_t r[4], uint32_t addr) {
    asm volatile("ldmatrix.sync.aligned.m8n8.x4.shared.b16 {%0,%1,%2,%3}, [%4];"
                 : "=r"(r[0]), "=r"(r[1]), "=r"(r[2]), "=r"(r[3]) : "r"(addr));
}

__device__ __forceinline__ void ldsm4t(uint32_t r[4], uint32_t addr) {
    asm volatile("ldmatrix.sync.aligned.m8n8.x4.trans.shared.b16 {%0,%1,%2,%3}, [%4];"
                 : "=r"(r[0]), "=r"(r[1]), "=r"(r[2]), "=r"(r[3]) : "r"(addr));
}

// ---------------- fused prep: xhalf + tables + W convert + zeroing ----------------
__global__ __launch_bounds__(256) void prep_all_kernel(const float* __restrict__ x,
                                                       const float* __restrict__ qk_w) {
    int idx = blockIdx.x * 256 + threadIdx.x;   // 0 .. 2M-1
    {
        size_t i = (size_t)idx;
        const float4* X4 = (const float4*)x;
        float4 a = X4[2 * i], b = X4[2 * i + 1];
        uint4 o;
        o.x = packh(__float2half_rn(a.x), __float2half_rn(a.y));
        o.y = packh(__float2half_rn(a.z), __float2half_rn(a.w));
        o.z = packh(__float2half_rn(b.x), __float2half_rn(b.y));
        o.w = packh(__float2half_rn(b.z), __float2half_rn(b.w));
        ((uint4*)g_xh)[i] = o;
    }
    if (idx < (DIMC / 2) * NPOS) {
        int j = idx >> 10, p = idx & (NPOS - 1);
        int jj = (j < 256) ? j : j - 256;
        float pos = (float)((j < 256) ? (p >> 5) : (p & 31));
        float theta = expf(-(float)jj * (9.210340371976184f / 256.f));
        float s, c;
        sincosf(pos * theta, &s, &c);
        g_cos[idx] = c;
        g_sin[idx] = s;
    }
    if (idx < 2 * DIMC * KPROJ) g_wf16[idx] = __float2half_rn(qk_w[idx]);
    if (idx < BATCHN * NH * HD * HD) g_kv[idx] = 0.f;
    if (idx < BATCHN * DIMC) g_km[idx] = 0.f;
}

// ---------------- projection GEMM: fp16, KCHUNK=64, 3-stage ring ----------------
#define PSTR 72
#define PB_STR 136
#define APLANE (128 * PSTR)                  // 9216
#define BPLANE (64 * PB_STR)                 // 8704
#define STG (APLANE + BPLANE)                // 17920 halves
#define NSTAGE 3
#define PROJ_SMEM (NSTAGE * STG * 2)         // 107520 bytes

__global__ __launch_bounds__(256) void proj_kernel(const float* __restrict__ qk_b) {
    extern __shared__ __align__(16) __half sm[];

    int tid = threadIdx.x;
    int lane = tid & 31, wid = tid >> 5;
    int wm = wid >> 2, wn = wid & 3;
    int g4 = lane >> 2, tg = lane & 3;
    int arow = (lane & 7) + ((lane >> 3) & 1) * 8;
    int acol = (lane >> 4) * 8;

    int pt = blockIdx.x, ot = blockIdx.y;
    int b = blockIdx.z >> 1, grp = blockIdx.z & 1;
    const __half* W = g_wf16 + (size_t)grp * DIMC * KPROJ;
    const __half* Xc = g_xh + ((size_t)b * DIMC + grp * KPROJ) * NPOS;
    int o0 = ot * 128, p0 = pt * 128;

    float c[4][4][4];
#pragma unroll
    for (int i = 0; i < 4; i++)
#pragma unroll
        for (int j = 0; j < 4; j++)
#pragma unroll
            for (int k = 0; k < 4; k++) c[i][j][k] = 0.f;

    uint32_t smem_base = cvta_sm(sm);

    auto issue = [&](int kt) {
        uint32_t st = smem_base + ((kt % NSTAGE) * STG) * 2;
        int c0 = kt * 64;
#pragma unroll
        for (int t = 0; t < 4; t++) {
            int i = tid + t * 256;
            int row = i >> 3, cs = (i & 7) * 8;
            cp16(st + (row * PSTR + cs) * 2, W + (size_t)(o0 + row) * KPROJ + c0 + cs);
        }
#pragma unroll
        for (int t = 0; t < 4; t++) {
            int i = tid + t * 256;
            int row = i >> 4, ch = (i & 15) * 8;
            cp16(st + (APLANE + row * PB_STR + ch) * 2,
                 Xc + (size_t)(c0 + row) * NPOS + p0 + ch);
        }
    };

    issue(0);
    asm volatile("cp.async.commit_group;");
    issue(1);
    asm volatile("cp.async.commit_group;");

    for (int kt = 0; kt < 8; kt++) {
        if (kt < 7) asm volatile("cp.async.wait_group 1;");
        else        asm volatile("cp.async.wait_group 0;");
        __syncthreads();

        uint32_t stA = smem_base + ((kt % NSTAGE) * STG) * 2;
        uint32_t stB = stA + APLANE * 2;

#pragma unroll
        for (int ks = 0; ks < 4; ks++) {
            int kk = ks * 16;
            uint32_t a4[4][4];
#pragma unroll
            for (int mi = 0; mi < 4; mi++)
                ldsm4(a4[mi], stA + ((wm * 64 + mi * 16 + arow) * PSTR + kk + acol) * 2);
            uint32_t bf[4][2];
#pragma unroll
            for (int nip = 0; nip < 2; nip++) {
                uint32_t r[4];
                ldsm4t(r, stB + ((kk + arow) * PB_STR + wn * 32 + nip * 16 + acol) * 2);
                bf[2 * nip][0] = r[0]; bf[2 * nip][1] = r[1];
                bf[2 * nip + 1][0] = r[2]; bf[2 * nip + 1][1] = r[3];
            }
#pragma unroll
            for (int mi = 0; mi < 4; mi++)
#pragma unroll
                for (int ni = 0; ni < 4; ni++)
                    mmaf16(c[mi][ni], a4[mi], bf[ni]);
        }

        if (kt + 2 < 8) {
            issue(kt + 2);
            asm volatile("cp.async.commit_group;");
        }
    }

    __half* dst = (grp ? g_kh : g_qh) + (size_t)b * DIMC * NPOS;
#pragma unroll
    for (int mi = 0; mi < 4; mi++) {
        int r0 = o0 + wm * 64 + mi * 16 + g4;
        int r1 = r0 + 8;
        float bias0 = __ldg(&qk_b[grp * DIMC + r0]);
        float bias1 = __ldg(&qk_b[grp * DIMC + r1]);
        float rs0 = 0.f, rs1 = 0.f;
#pragma unroll
        for (int ni = 0; ni < 4; ni++) {
            int p = p0 + wn * 32 + ni * 8 + tg * 2;
            float v00 = elu1(c[mi][ni][0] + bias0);
            float v01 = elu1(c[mi][ni][1] + bias0);
            float v10 = elu1(c[mi][ni][2] + bias1);
            float v11 = elu1(c[mi][ni][3] + bias1);
            *(uint32_t*)&dst[(size_t)r0 * NPOS + p] = packh(__float2half_rn(v00), __float2half_rn(v01));
            *(uint32_t*)&dst[(size_t)r1 * NPOS + p] = packh(__float2half_rn(v10), __float2half_rn(v11));
            rs0 += v00 + v01;
            rs1 += v10 + v11;
        }
        if (grp) {
            rs0 += __shfl_xor_sync(0xffffffffu, rs0, 1);
            rs0 += __shfl_xor_sync(0xffffffffu, rs0, 2);
            rs1 += __shfl_xor_sync(0xffffffffu, rs1, 1);
            rs1 += __shfl_xor_sync(0xffffffffu, rs1, 2);
            if (tg == 0) {
                atomicAdd(&g_km[b * DIMC + r0], rs0 * (1.f / NPOS));
                atomicAdd(&g_km[b * DIMC + r1], rs1 * (1.f / NPOS));
            }
        }
    }
}

// ---------------- kv kernel (n-split x8): rope k staging, fp16 V, 1 MMA ----------------
#define KV_STR 72

__global__ __launch_bounds__(256) void kv_kernel() {
    __shared__ __align__(16) __half sa[64 * KV_STR];      // rope(k) [d][n]
    __shared__ __align__(16) __half sb[64 * KV_STR];      // v fp16  [e][n]

    int tid = threadIdx.x;
    int lane = tid & 31, wid = tid >> 5;
    int wm = wid >> 2, wn = wid & 3;
    int g4 = lane >> 2, tg = lane & 3;
    int bh = blockIdx.x, chunk = blockIdx.y;
    int b = bh >> 4, h = bh & 15;
    size_t base = ((size_t)b * DIMC + h * HD) * NPOS;
    const __half* K = g_kh + base;
    const __half* V = g_xh + base;

    int kd2 = tid >> 3, kng = (tid & 7) * 8;
    int ve = tid >> 2, vng = (tid & 3) * 16;

    float c[2][2][4];
#pragma unroll
    for (int i = 0; i < 2; i++)
#pragma unroll
        for (int j = 0; j < 2; j++)
#pragma unroll
            for (int k = 0; k < 4; k++) c[i][j][k] = 0.f;

    for (int sub = 0; sub < 2; sub++) {
        int n0 = chunk * 128 + sub * 64;
        {
            int r0 = 2 * kd2, r1 = r0 + 1;
            size_t o0 = (size_t)r0 * NPOS + n0 + kng;
            size_t o1 = o0 + NPOS;
            uint4 kh0 = *(const uint4*)&K[o0];
            uint4 kh1 = *(const uint4*)&K[o1];
            const __half* p0 = (const __half*)&kh0;
            const __half* p1 = (const __half*)&kh1;
            int j = h * 32 + kd2;
            const float* Cp = &g_cos[(size_t)j * NPOS + n0 + kng];
            const float* Sp = &g_sin[(size_t)j * NPOS + n0 + kng];
            float4 cA = *(const float4*)Cp, cB = *(const float4*)(Cp + 4);
            float4 sA = *(const float4*)Sp, sB = *(const float4*)(Sp + 4);
            float csv[8] = {cA.x, cA.y, cA.z, cA.w, cB.x, cB.y, cB.z, cB.w};
            float snv[8] = {sA.x, sA.y, sA.z, sA.w, sB.x, sB.y, sB.z, sB.w};
            __half oh0[8], oh1[8];
#pragma unroll
            for (int t = 0; t < 8; t++) {
                float k0 = __half2float(p0[t]);
                float k1 = __half2float(p1[t]);
                oh0[t] = __float2half_rn(csv[t] * k0 - snv[t] * k1);
                oh1[t] = __float2half_rn(snv[t] * k0 + csv[t] * k1);
            }
            *(uint4*)&sa[r0 * KV_STR + kng] = *(uint4*)oh0;
            *(uint4*)&sa[r1 * KV_STR + kng] = *(uint4*)oh1;
        }
        {
            const __half* Vp = &V[(size_t)ve * NPOS + n0 + vng];
            *(uint4*)&sb[ve * KV_STR + vng] = *(const uint4*)Vp;
            *(uint4*)&sb[ve * KV_STR + vng + 8] = *(const uint4*)(Vp + 8);
        }
        __syncthreads();

#pragma unroll
        for (int ks = 0; ks < 4; ks++) {
            int kk = ks * 16;
            int col = kk + tg * 2;
            uint32_t ah[2][4];
#pragma unroll
            for (int mi = 0; mi < 2; mi++) {
                int d = wm * 32 + mi * 16 + g4;
                ah[mi][0] = *(uint32_t*)&sa[d * KV_STR + col];
                ah[mi][1] = *(uint32_t*)&sa[(d + 8) * KV_STR + col];
                ah[mi][2] = *(uint32_t*)&sa[d * KV_STR + col + 8];
                ah[mi][3] = *(uint32_t*)&sa[(d + 8) * KV_STR + col + 8];
            }
            uint32_t bv[2][2];
#pragma unroll
            for (int ni = 0; ni < 2; ni++) {
                int e = wn * 16 + ni * 8 + g4;
                bv[ni][0] = *(uint32_t*)&sb[e * KV_STR + col];
                bv[ni][1] = *(uint32_t*)&sb[e * KV_STR + col + 8];
            }
#pragma unroll
            for (int mi = 0; mi < 2; mi++)
#pragma unroll
                for (int ni = 0; ni < 2; ni++)
                    mmaf16(c[mi][ni], ah[mi], bv[ni]);
        }
        __syncthreads();
    }

    float* KV = g_kv + (size_t)bh * HD * HD;
#pragma unroll
    for (int mi = 0; mi < 2; mi++) {
#pragma unroll
        for (int ni = 0; ni < 2; ni++) {
            int d0 = wm * 32 + mi * 16 + g4, d1 = d0 + 8;
            int e0 = wn * 16 + ni * 8 + tg * 2, e1 = e0 + 1;
            atomicAdd(&KV[e0 * HD + d0], c[mi][ni][0] * (1.f / NPOS));
            atomicAdd(&KV[e1 * HD + d0], c[mi][ni][1] * (1.f / NPOS));
            atomicAdd(&KV[e0 * HD + d1], c[mi][ni][2] * (1.f / NPOS));
            atomicAdd(&KV[e1 * HD + d1], c[mi][ni][3] * (1.f / NPOS));
        }
    }
}

// ---------------- out kernel: 512 threads, cooperative lepe in reused smem ----------------
#define OA_STR 66
#define OB_STR 72
#define FRONT_HALVES (128 * OA_STR + 2 * 64 * OB_STR)    // 17664 halves = 35328 B (>= 64*132*4)
#define OSMEM_BYTES (FRONT_HALVES * 2 + (128 + 576 + 64 + 64 * 198) * 4)

__global__ __launch_bounds__(512, 2) void out_kernel(float* __restrict__ out,
                                                     const float* __restrict__ lepe_w,
                                                     const float* __restrict__ lepe_b) {
    extern __shared__ __align__(16) char sm_raw[];
    __half* sa = (__half*)sm_raw;              // roped q [n][d] 128 x OA_STR
    __half* skh = sa + 128 * OA_STR;
    __half* skl = skh + 64 * OB_STR;
    float* s_z = (float*)(sm_raw + FRONT_HALVES * 2);
    float* sw = s_z + 128;
    float* sbias = sw + 576;
    float* sx = sbias + 64;                    // [e][6 rows][33]

    int tid = threadIdx.x;
    int lane = tid & 31, wid = tid >> 5;
    int wm = wid >> 2, wn = wid & 3;           // 4 n-groups x 4 e-groups
    int g4 = lane >> 2, tg = lane & 3;

    int nt = blockIdx.x, bh = blockIdx.y;
    int b = bh >> 4, h = bh & 15;
    int n0 = nt * 128;
    int y0 = nt * 4;
    size_t qbase = ((size_t)b * DIMC + h * HD) * NPOS;
    const __half* Q = g_qh + qbase;
    const __half* Xh = g_xh + qbase;
    const float* km = g_km + b * DIMC + h * HD;

    if (tid < 128) s_z[tid] = 0.f;
    // stage kv hi/lo
    {
        const float* KV = g_kv + (size_t)bh * HD * HD;
        for (int i = tid; i < 4096; i += 512) {
            int e = i >> 6, d = i & 63;
            __half hi, lo;
            splith(KV[i], hi, lo);
            skh[e * OB_STR + d] = hi;
            skl[e * OB_STR + d] = lo;
        }
    }
    for (int i = tid; i < 576; i += 512) sw[i] = __ldg(&lepe_w[h * 576 + i]);
    if (tid < 64) sbias[tid] = __ldg(&lepe_b[h * 64 + tid]);
    // stage x halo rows from fp16 plane
    {
        for (int i = tid; i < 1536; i += 512) {
            int e = i / 24;
            int rem = i - e * 24;
            int rr = rem >> 2, q8 = (rem & 3) * 8;
            int yy = y0 - 1 + rr;
            float vf[8];
            if (yy >= 0 && yy < 32) {
                uint4 v = *(const uint4*)&Xh[(size_t)e * 1024 + yy * 32 + q8];
                const __half* ph = (const __half*)&v;
#pragma unroll
                for (int t = 0; t < 8; t++) vf[t] = __half2float(ph[t]);
            } else {
#pragma unroll
                for (int t = 0; t < 8; t++) vf[t] = 0.f;
            }
            float* d = &sx[e * 198 + rr * 33 + q8];
#pragma unroll
            for (int t = 0; t < 8; t++) d[t] = vf[t];
        }
    }
    __syncthreads();

    // stage rope(q) + z partial
    float zacc = 0.f;
    int nfix = tid & 127;
    int quarter = tid >> 7;
#pragma unroll 4
    for (int pass = 0; pass < 8; pass++) {
        int d2 = quarter + pass * 4;
        size_t i0 = (size_t)(2 * d2) * NPOS + n0 + nfix;
        size_t i1 = i0 + NPOS;
        float q0 = __half2float(Q[i0]);
        float q1 = __half2float(Q[i1]);
        float km0 = __ldg(&km[2 * d2]);
        float km1 = __ldg(&km[2 * d2 + 1]);
        zacc += q0 * km0 + q1 * km1;
        int j = h * 32 + d2;
        float cs = g_cos[(size_t)j * NPOS + n0 + nfix];
        float sn = g_sin[(size_t)j * NPOS + n0 + nfix];
        float r0 = cs * q0 - sn * q1;
        float r1 = sn * q0 + cs * q1;
        *(uint32_t*)&sa[nfix * OA_STR + 2 * d2] = packh(__float2half_rn(r0), __float2half_rn(r1));
    }
    atomicAdd(&s_z[nfix], zacc);
    __syncthreads();

    float c[2][2][4];
#pragma unroll
    for (int i = 0; i < 2; i++)
#pragma unroll
        for (int j = 0; j < 2; j++)
#pragma unroll
            for (int k = 0; k < 4; k++) c[i][j][k] = 0.f;

#pragma unroll
    for (int ks = 0; ks < 4; ks++) {
        int kk = ks * 16;
        int col = kk + tg * 2;
        uint32_t ah[2][4];
#pragma unroll
        for (int mi = 0; mi < 2; mi++) {
            int n = wm * 32 + mi * 16 + g4;
            ah[mi][0] = *(uint32_t*)&sa[n * OA_STR + col];
            ah[mi][1] = *(uint32_t*)&sa[(n + 8) * OA_STR + col];
            ah[mi][2] = *(uint32_t*)&sa[n * OA_STR + col + 8];
            ah[mi][3] = *(uint32_t*)&sa[(n + 8) * OA_STR + col + 8];
        }
        uint32_t bh2[2][2], bl2[2][2];
#pragma unroll
        for (int ni = 0; ni < 2; ni++) {
            int e = wn * 16 + ni * 8 + g4;
            bh2[ni][0] = *(uint32_t*)&skh[e * OB_STR + col];
            bh2[ni][1] = *(uint32_t*)&skh[e * OB_STR + col + 8];
            bl2[ni][0] = *(uint32_t*)&skl[e * OB_STR + col];
            bl2[ni][1] = *(uint32_t*)&skl[e * OB_STR + col + 8];
        }
#pragma unroll
        for (int mi = 0; mi < 2; mi++)
#pragma unroll
            for (int ni = 0; ni < 2; ni++) {
                mmaf16(c[mi][ni], ah[mi], bh2[ni]);
                mmaf16(c[mi][ni], ah[mi], bl2[ni]);
            }
    }

    // ---- cooperative lepe: reuse sa/skh/skl region as fp32 plane [e][132] ----
    __syncthreads();   // all MMA reads of sa/skh/skl complete
    float* slepe = (float*)sm_raw;
#pragma unroll
    for (int it = 0; it < 2; it++) {
        int u = it * 512 + tid;           // 1024 units: (e, 8-px segment)
        int e = u >> 4, seg = u & 15;
        int y = seg >> 2, x0 = (seg & 3) * 8;
        const float* wv = &sw[e * 9];
        float acc[8];
        float bs = sbias[e];
#pragma unroll
        for (int t = 0; t < 8; t++) acc[t] = bs;
#pragma unroll
        for (int i = 0; i < 3; i++) {
            const float* rw = &sx[e * 198 + (y + i) * 33 + x0];
            float r[10];
            r[0] = (x0 > 0) ? rw[-1] : 0.f;
#pragma unroll
            for (int t = 0; t < 8; t++) r[t + 1] = rw[t];
            r[9] = (x0 + 8 < 32) ? rw[8] : 0.f;
            float w0 = wv[i * 3 + 0], w1 = wv[i * 3 + 1], w2 = wv[i * 3 + 2];
#pragma unroll
            for (int t = 0; t < 8; t++)
                acc[t] += w0 * r[t] + w1 * r[t + 1] + w2 * r[t + 2];
        }
        float4* d = (float4*)&slepe[e * 132 + y * 32 + x0];
        d[0] = make_float4(acc[0], acc[1], acc[2], acc[3]);
        d[1] = make_float4(acc[4], acc[5], acc[6], acc[7]);
    }
    __syncthreads();

    // epilogue: z scale + lepe read + STG
    float* O = out + qbase;
#pragma unroll
    for (int ni = 0; ni < 2; ni++) {
        int e0 = wn * 16 + ni * 8 + tg * 2;
        int e1 = e0 + 1;
#pragma unroll
        for (int mi = 0; mi < 2; mi++) {
            int nr0 = wm * 32 + mi * 16 + g4;
            int nr1 = nr0 + 8;
            float z0 = 1.f / (s_z[nr0] + 1e-6f);
            float z1 = 1.f / (s_z[nr1] + 1e-6f);
            size_t i00 = (size_t)e0 * NPOS + n0 + nr0;
            size_t i01 = (size_t)e1 * NPOS + n0 + nr0;
            size_t i10 = (size_t)e0 * NPOS + n0 + nr1;
            size_t i11 = (size_t)e1 * NPOS + n0 + nr1;
            O[i00] = c[mi][ni][0] * z0 + slepe[e0 * 132 + nr0];
            O[i01] = c[mi][ni][1] * z0 + slepe[e1 * 132 + nr0];
            O[i10] = c[mi][ni][2] * z1 + slepe[e0 * 132 + nr1];
            O[i11] = c[mi][ni][3] * z1 + slepe[e1 * 132 + nr1];
        }
    }
}

// ---------------- launch ----------------
extern "C" void kernel_launch(void* const* d_in, const int* in_sizes, int n_in,
                              void* d_out, int out_size) {
    const float* x      = (const float*)d_in[0];
    const float* qk_w   = (const float*)d_in[1];
    const float* qk_b   = (const float*)d_in[2];
    const float* lepe_w = (const float*)d_in[3];
    const float* lepe_b = (const float*)d_in[4];
    float* out = (float*)d_out;

    cudaFuncSetAttribute(proj_kernel, cudaFuncAttributeMaxDynamicSharedMemorySize, PROJ_SMEM);
    cudaFuncSetAttribute(out_kernel, cudaFuncAttributeMaxDynamicSharedMemorySize, OSMEM_BYTES);

    // launches: prep(1) proj(2) kv(3) out(4) -> ncu capture slot = out
    prep_all_kernel<<<BATCHN * DIMC * NPOS / 8 / 256, 256>>>(x, qk_w);
    proj_kernel<<<dim3(8, 8, 2 * BATCHN), 256, PROJ_SMEM>>>(qk_b);
    kv_kernel<<<dim3(BATCHN * NH, 8), 256>>>();
    out_kernel<<<dim3(8, BATCHN * NH), 512, OSMEM_BYTES>>>(out, lepe_w, lepe_b);
}

// round 17
// speedup vs baseline: 1.2491x; 1.0081x over previous
#include <cuda_runtime.h>
#include <cuda_fp16.h>
#include <cstdint>
#include <math.h>

#define DIMC 1024
#define NH   16
#define HD   64
#define NPOS 1024
#define BATCHN 16
#define KPROJ 512

// ---------------- scratch ----------------
__device__ __half g_wf16[2 * DIMC * KPROJ];                 // W rounded fp16
__device__ __half g_xh[BATCHN * DIMC * NPOS];               // x fp16, native [b][c][p]
__device__ __half g_qh[BATCHN * DIMC * NPOS];               // unroped q fp16 [b][o][p]
__device__ __half g_kh[BATCHN * DIMC * NPOS];               // unroped k
__device__ float g_km[BATCHN * DIMC];
__device__ float g_kv[BATCHN * NH * HD * HD];               // [bh][e][d] fp32 accum
__device__ __half2 g_cs[(DIMC / 2) * NPOS];                 // packed (cos, sin) [j][p]

// ---------------- helpers ----------------
__device__ __forceinline__ void mmaf16(float c[4], const uint32_t a[4], const uint32_t b[2]) {
    asm volatile(
        "mma.sync.aligned.m16n8k16.row.col.f32.f16.f16.f32 "
        "{%0,%1,%2,%3}, {%4,%5,%6,%7}, {%8,%9}, {%0,%1,%2,%3};"
        : "+f"(c[0]), "+f"(c[1]), "+f"(c[2]), "+f"(c[3])
        : "r"(a[0]), "r"(a[1]), "r"(a[2]), "r"(a[3]), "r"(b[0]), "r"(b[1]));
}

__device__ __forceinline__ void splith(float v, __half& hi, __half& lo) {
    hi = __float2half_rn(v);
    lo = __float2half_rn(v - __half2float(hi));
}

__device__ __forceinline__ uint32_t packh(__half a, __half b) {
    return (uint32_t)__half_as_ushort(a) | ((uint32_t)__half_as_ushort(b) << 16);
}

__device__ __forceinline__ float elu1(float v) { return v > 0.f ? v + 1.f : expf(v); }

__device__ __forceinline__ uint32_t cvta_sm(const void* p) {
    return (uint32_t)__cvta_generic_to_shared(p);
}

__device__ __forceinline__ void cp16(uint32_t saddr, const void* g) {
    asm volatile("cp.async.cg.shared.global [%0], [%1], 16;" :: "r"(saddr), "l"(g));
}

__device__ __forceinline__ void ldsm4(uint32_t r[4], uint32_t addr) {
    asm volatile("ldmatrix.sync.aligned.m8n8.x4.shared.b16 {%0,%1,%2,%3}, [%4];"
                 : "=r"(r[0]), "=r"(r[1]), "=r"(r[2]), "=r"(r[3]) : "r"(addr));
}

__device__ __forceinline__ void ldsm4t(uint32_t r[4], uint32_t addr) {
    asm volatile("ldmatrix.sync.aligned.m8n8.x4.trans.shared.b16 {%0,%1,%2,%3}, [%4];"
                 : "=r"(r[0]), "=r"(r[1]), "=r"(r[2]), "=r"(r[3]) : "r"(addr));
}

// ---------------- fused prep: xhalf + packed tables + W convert + zeroing ----------------
__global__ __launch_bounds__(256) void prep_all_kernel(const float* __restrict__ x,
                                                       const float* __restrict__ qk_w) {
    int idx = blockIdx.x * 256 + threadIdx.x;   // 0 .. 2M-1
    {
        size_t i = (size_t)idx;
        const float4* X4 = (const float4*)x;
        float4 a = X4[2 * i], b = X4[2 * i + 1];
        uint4 o;
        o.x = packh(__float2half_rn(a.x), __float2half_rn(a.y));
        o.y = packh(__float2half_rn(a.z), __float2half_rn(a.w));
        o.z = packh(__float2half_rn(b.x), __float2half_rn(b.y));
        o.w = packh(__float2half_rn(b.z), __float2half_rn(b.w));
        ((uint4*)g_xh)[i] = o;
    }
    if (idx < (DIMC / 2) * NPOS) {
        int j = idx >> 10, p = idx & (NPOS - 1);
        int jj = (j < 256) ? j : j - 256;
        float pos = (float)((j < 256) ? (p >> 5) : (p & 31));
        float theta = expf(-(float)jj * (9.210340371976184f / 256.f));
        float s, c;
        sincosf(pos * theta, &s, &c);
        g_cs[idx] = __floats2half2_rn(c, s);
    }
    if (idx < 2 * DIMC * KPROJ) g_wf16[idx] = __float2half_rn(qk_w[idx]);
    if (idx < BATCHN * NH * HD * HD) g_kv[idx] = 0.f;
    if (idx < BATCHN * DIMC) g_km[idx] = 0.f;
}

// ---------------- projection GEMM: fp16, KCHUNK=64, 3-stage ring ----------------
#define PSTR 72
#define PB_STR 136
#define APLANE (128 * PSTR)                  // 9216
#define BPLANE (64 * PB_STR)                 // 8704
#define STG (APLANE + BPLANE)                // 17920 halves
#define NSTAGE 3
#define PROJ_SMEM (NSTAGE * STG * 2)         // 107520 bytes

__global__ __launch_bounds__(256) void proj_kernel(const float* __restrict__ qk_b) {
    extern __shared__ __align__(16) __half sm[];

    int tid = threadIdx.x;
    int lane = tid & 31, wid = tid >> 5;
    int wm = wid >> 2, wn = wid & 3;
    int g4 = lane >> 2, tg = lane & 3;
    int arow = (lane & 7) + ((lane >> 3) & 1) * 8;
    int acol = (lane >> 4) * 8;

    int pt = blockIdx.x, ot = blockIdx.y;
    int b = blockIdx.z >> 1, grp = blockIdx.z & 1;
    const __half* W = g_wf16 + (size_t)grp * DIMC * KPROJ;
    const __half* Xc = g_xh + ((size_t)b * DIMC + grp * KPROJ) * NPOS;
    int o0 = ot * 128, p0 = pt * 128;

    float c[4][4][4];
#pragma unroll
    for (int i = 0; i < 4; i++)
#pragma unroll
        for (int j = 0; j < 4; j++)
#pragma unroll
            for (int k = 0; k < 4; k++) c[i][j][k] = 0.f;

    uint32_t smem_base = cvta_sm(sm);

    auto issue = [&](int kt) {
        uint32_t st = smem_base + ((kt % NSTAGE) * STG) * 2;
        int c0 = kt * 64;
#pragma unroll
        for (int t = 0; t < 4; t++) {
            int i = tid + t * 256;
            int row = i >> 3, cs = (i & 7) * 8;
            cp16(st + (row * PSTR + cs) * 2, W + (size_t)(o0 + row) * KPROJ + c0 + cs);
        }
#pragma unroll
        for (int t = 0; t < 4; t++) {
            int i = tid + t * 256;
            int row = i >> 4, ch = (i & 15) * 8;
            cp16(st + (APLANE + row * PB_STR + ch) * 2,
                 Xc + (size_t)(c0 + row) * NPOS + p0 + ch);
        }
    };

    issue(0);
    asm volatile("cp.async.commit_group;");
    issue(1);
    asm volatile("cp.async.commit_group;");

    for (int kt = 0; kt < 8; kt++) {
        if (kt < 7) asm volatile("cp.async.wait_group 1;");
        else        asm volatile("cp.async.wait_group 0;");
        __syncthreads();

        uint32_t stA = smem_base + ((kt % NSTAGE) * STG) * 2;
        uint32_t stB = stA + APLANE * 2;

#pragma unroll
        for (int ks = 0; ks < 4; ks++) {
            int kk = ks * 16;
            uint32_t a4[4][4];
#pragma unroll
            for (int mi = 0; mi < 4; mi++)
                ldsm4(a4[mi], stA + ((wm * 64 + mi * 16 + arow) * PSTR + kk + acol) * 2);
            uint32_t bf[4][2];
#pragma unroll
            for (int nip = 0; nip < 2; nip++) {
                uint32_t r[4];
                ldsm4t(r, stB + ((kk + arow) * PB_STR + wn * 32 + nip * 16 + acol) * 2);
                bf[2 * nip][0] = r[0]; bf[2 * nip][1] = r[1];
                bf[2 * nip + 1][0] = r[2]; bf[2 * nip + 1][1] = r[3];
            }
#pragma unroll
            for (int mi = 0; mi < 4; mi++)
#pragma unroll
                for (int ni = 0; ni < 4; ni++)
                    mmaf16(c[mi][ni], a4[mi], bf[ni]);
        }

        if (kt + 2 < 8) {
            issue(kt + 2);
            asm volatile("cp.async.commit_group;");
        }
    }

    __half* dst = (grp ? g_kh : g_qh) + (size_t)b * DIMC * NPOS;
#pragma unroll
    for (int mi = 0; mi < 4; mi++) {
        int r0 = o0 + wm * 64 + mi * 16 + g4;
        int r1 = r0 + 8;
        float bias0 = __ldg(&qk_b[grp * DIMC + r0]);
        float bias1 = __ldg(&qk_b[grp * DIMC + r1]);
        float rs0 = 0.f, rs1 = 0.f;
#pragma unroll
        for (int ni = 0; ni < 4; ni++) {
            int p = p0 + wn * 32 + ni * 8 + tg * 2;
            float v00 = elu1(c[mi][ni][0] + bias0);
            float v01 = elu1(c[mi][ni][1] + bias0);
            float v10 = elu1(c[mi][ni][2] + bias1);
            float v11 = elu1(c[mi][ni][3] + bias1);
            *(uint32_t*)&dst[(size_t)r0 * NPOS + p] = packh(__float2half_rn(v00), __float2half_rn(v01));
            *(uint32_t*)&dst[(size_t)r1 * NPOS + p] = packh(__float2half_rn(v10), __float2half_rn(v11));
            rs0 += v00 + v01;
            rs1 += v10 + v11;
        }
        if (grp) {
            rs0 += __shfl_xor_sync(0xffffffffu, rs0, 1);
            rs0 += __shfl_xor_sync(0xffffffffu, rs0, 2);
            rs1 += __shfl_xor_sync(0xffffffffu, rs1, 1);
            rs1 += __shfl_xor_sync(0xffffffffu, rs1, 2);
            if (tg == 0) {
                atomicAdd(&g_km[b * DIMC + r0], rs0 * (1.f / NPOS));
                atomicAdd(&g_km[b * DIMC + r1], rs1 * (1.f / NPOS));
            }
        }
    }
}

// ---------------- kv kernel (n-split x8): rope k staging (packed tables), fp16 V ----------------
#define KV_STR 72

__global__ __launch_bounds__(256) void kv_kernel() {
    __shared__ __align__(16) __half sa[64 * KV_STR];      // rope(k) [d][n]
    __shared__ __align__(16) __half sb[64 * KV_STR];      // v fp16  [e][n]

    int tid = threadIdx.x;
    int lane = tid & 31, wid = tid >> 5;
    int wm = wid >> 2, wn = wid & 3;
    int g4 = lane >> 2, tg = lane & 3;
    int bh = blockIdx.x, chunk = blockIdx.y;
    int b = bh >> 4, h = bh & 15;
    size_t base = ((size_t)b * DIMC + h * HD) * NPOS;
    const __half* K = g_kh + base;
    const __half* V = g_xh + base;

    int kd2 = tid >> 3, kng = (tid & 7) * 8;
    int ve = tid >> 2, vng = (tid & 3) * 16;

    float c[2][2][4];
#pragma unroll
    for (int i = 0; i < 2; i++)
#pragma unroll
        for (int j = 0; j < 2; j++)
#pragma unroll
            for (int k = 0; k < 4; k++) c[i][j][k] = 0.f;

    for (int sub = 0; sub < 2; sub++) {
        int n0 = chunk * 128 + sub * 64;
        {
            int r0 = 2 * kd2, r1 = r0 + 1;
            size_t o0 = (size_t)r0 * NPOS + n0 + kng;
            size_t o1 = o0 + NPOS;
            uint4 kh0 = *(const uint4*)&K[o0];
            uint4 kh1 = *(const uint4*)&K[o1];
            const __half* p0 = (const __half*)&kh0;
            const __half* p1 = (const __half*)&kh1;
            int j = h * 32 + kd2;
            const __half2* CS = &g_cs[(size_t)j * NPOS + n0 + kng];
            uint4 csA = *(const uint4*)CS;
            uint4 csB = *(const uint4*)(CS + 4);
            const __half2* csp = (const __half2*)&csA;   // 4 half2
            const __half2* csq = (const __half2*)&csB;
            __half oh0[8], oh1[8];
#pragma unroll
            for (int t = 0; t < 8; t++) {
                float2 cs2 = __half22float2((t < 4) ? csp[t] : csq[t - 4]);
                float k0 = __half2float(p0[t]);
                float k1 = __half2float(p1[t]);
                oh0[t] = __float2half_rn(cs2.x * k0 - cs2.y * k1);
                oh1[t] = __float2half_rn(cs2.y * k0 + cs2.x * k1);
            }
            *(uint4*)&sa[r0 * KV_STR + kng] = *(uint4*)oh0;
            *(uint4*)&sa[r1 * KV_STR + kng] = *(uint4*)oh1;
        }
        {
            const __half* Vp = &V[(size_t)ve * NPOS + n0 + vng];
            *(uint4*)&sb[ve * KV_STR + vng] = *(const uint4*)Vp;
            *(uint4*)&sb[ve * KV_STR + vng + 8] = *(const uint4*)(Vp + 8);
        }
        __syncthreads();

#pragma unroll
        for (int ks = 0; ks < 4; ks++) {
            int kk = ks * 16;
            int col = kk + tg * 2;
            uint32_t ah[2][4];
#pragma unroll
            for (int mi = 0; mi < 2; mi++) {
                int d = wm * 32 + mi * 16 + g4;
                ah[mi][0] = *(uint32_t*)&sa[d * KV_STR + col];
                ah[mi][1] = *(uint32_t*)&sa[(d + 8) * KV_STR + col];
                ah[mi][2] = *(uint32_t*)&sa[d * KV_STR + col + 8];
                ah[mi][3] = *(uint32_t*)&sa[(d + 8) * KV_STR + col + 8];
            }
            uint32_t bv[2][2];
#pragma unroll
            for (int ni = 0; ni < 2; ni++) {
                int e = wn * 16 + ni * 8 + g4;
                bv[ni][0] = *(uint32_t*)&sb[e * KV_STR + col];
                bv[ni][1] = *(uint32_t*)&sb[e * KV_STR + col + 8];
            }
#pragma unroll
            for (int mi = 0; mi < 2; mi++)
#pragma unroll
                for (int ni = 0; ni < 2; ni++)
                    mmaf16(c[mi][ni], ah[mi], bv[ni]);
        }
        __syncthreads();
    }

    float* KV = g_kv + (size_t)bh * HD * HD;
#pragma unroll
    for (int mi = 0; mi < 2; mi++) {
#pragma unroll
        for (int ni = 0; ni < 2; ni++) {
            int d0 = wm * 32 + mi * 16 + g4, d1 = d0 + 8;
            int e0 = wn * 16 + ni * 8 + tg * 2, e1 = e0 + 1;
            atomicAdd(&KV[e0 * HD + d0], c[mi][ni][0] * (1.f / NPOS));
            atomicAdd(&KV[e1 * HD + d0], c[mi][ni][1] * (1.f / NPOS));
            atomicAdd(&KV[e0 * HD + d1], c[mi][ni][2] * (1.f / NPOS));
            atomicAdd(&KV[e1 * HD + d1], c[mi][ni][3] * (1.f / NPOS));
        }
    }
}

// ---------------- out kernel: 512 threads, cooperative lepe, packed tables ----------------
#define OA_STR 66
#define OB_STR 72
#define FRONT_HALVES (128 * OA_STR + 2 * 64 * OB_STR)
#define OSMEM_BYTES (FRONT_HALVES * 2 + (128 + 576 + 64 + 64 * 198) * 4)

__global__ __launch_bounds__(512, 2) void out_kernel(float* __restrict__ out,
                                                     const float* __restrict__ lepe_w,
                                                     const float* __restrict__ lepe_b) {
    extern __shared__ __align__(16) char sm_raw[];
    __half* sa = (__half*)sm_raw;              // roped q [n][d] 128 x OA_STR
    __half* skh = sa + 128 * OA_STR;
    __half* skl = skh + 64 * OB_STR;
    float* s_z = (float*)(sm_raw + FRONT_HALVES * 2);
    float* sw = s_z + 128;
    float* sbias = sw + 576;
    float* sx = sbias + 64;                    // [e][6 rows][33]

    int tid = threadIdx.x;
    int lane = tid & 31, wid = tid >> 5;
    int wm = wid >> 2, wn = wid & 3;
    int g4 = lane >> 2, tg = lane & 3;

    int nt = blockIdx.x, bh = blockIdx.y;
    int b = bh >> 4, h = bh & 15;
    int n0 = nt * 128;
    int y0 = nt * 4;
    size_t qbase = ((size_t)b * DIMC + h * HD) * NPOS;
    const __half* Q = g_qh + qbase;
    const __half* Xh = g_xh + qbase;
    const float* km = g_km + b * DIMC + h * HD;

    if (tid < 128) s_z[tid] = 0.f;
    {
        const float* KV = g_kv + (size_t)bh * HD * HD;
        for (int i = tid; i < 4096; i += 512) {
            int e = i >> 6, d = i & 63;
            __half hi, lo;
            splith(KV[i], hi, lo);
            skh[e * OB_STR + d] = hi;
            skl[e * OB_STR + d] = lo;
        }
    }
    for (int i = tid; i < 576; i += 512) sw[i] = __ldg(&lepe_w[h * 576 + i]);
    if (tid < 64) sbias[tid] = __ldg(&lepe_b[h * 64 + tid]);
    {
        for (int i = tid; i < 1536; i += 512) {
            int e = i / 24;
            int rem = i - e * 24;
            int rr = rem >> 2, q8 = (rem & 3) * 8;
            int yy = y0 - 1 + rr;
            float vf[8];
            if (yy >= 0 && yy < 32) {
                uint4 v = *(const uint4*)&Xh[(size_t)e * 1024 + yy * 32 + q8];
                const __half* ph = (const __half*)&v;
#pragma unroll
                for (int t = 0; t < 8; t++) vf[t] = __half2float(ph[t]);
            } else {
#pragma unroll
                for (int t = 0; t < 8; t++) vf[t] = 0.f;
            }
            float* d = &sx[e * 198 + rr * 33 + q8];
#pragma unroll
            for (int t = 0; t < 8; t++) d[t] = vf[t];
        }
    }
    __syncthreads();

    // stage rope(q) + z partial with packed tables
    float zacc = 0.f;
    int nfix = tid & 127;
    int quarter = tid >> 7;
#pragma unroll 4
    for (int pass = 0; pass < 8; pass++) {
        int d2 = quarter + pass * 4;
        size_t i0 = (size_t)(2 * d2) * NPOS + n0 + nfix;
        size_t i1 = i0 + NPOS;
        float q0 = __half2float(Q[i0]);
        float q1 = __half2float(Q[i1]);
        float km0 = __ldg(&km[2 * d2]);
        float km1 = __ldg(&km[2 * d2 + 1]);
        zacc += q0 * km0 + q1 * km1;
        int j = h * 32 + d2;
        float2 cs2 = __half22float2(g_cs[(size_t)j * NPOS + n0 + nfix]);
        float r0 = cs2.x * q0 - cs2.y * q1;
        float r1 = cs2.y * q0 + cs2.x * q1;
        *(uint32_t*)&sa[nfix * OA_STR + 2 * d2] = packh(__float2half_rn(r0), __float2half_rn(r1));
    }
    atomicAdd(&s_z[nfix], zacc);
    __syncthreads();

    float c[2][2][4];
#pragma unroll
    for (int i = 0; i < 2; i++)
#pragma unroll
        for (int j = 0; j < 2; j++)
#pragma unroll
            for (int k = 0; k < 4; k++) c[i][j][k] = 0.f;

#pragma unroll
    for (int ks = 0; ks < 4; ks++) {
        int kk = ks * 16;
        int col = kk + tg * 2;
        uint32_t ah[2][4];
#pragma unroll
        for (int mi = 0; mi < 2; mi++) {
            int n = wm * 32 + mi * 16 + g4;
            ah[mi][0] = *(uint32_t*)&sa[n * OA_STR + col];
            ah[mi][1] = *(uint32_t*)&sa[(n + 8) * OA_STR + col];
            ah[mi][2] = *(uint32_t*)&sa[n * OA_STR + col + 8];
            ah[mi][3] = *(uint32_t*)&sa[(n + 8) * OA_STR + col + 8];
        }
        uint32_t bh2[2][2], bl2[2][2];
#pragma unroll
        for (int ni = 0; ni < 2; ni++) {
            int e = wn * 16 + ni * 8 + g4;
            bh2[ni][0] = *(uint32_t*)&skh[e * OB_STR + col];
            bh2[ni][1] = *(uint32_t*)&skh[e * OB_STR + col + 8];
            bl2[ni][0] = *(uint32_t*)&skl[e * OB_STR + col];
            bl2[ni][1] = *(uint32_t*)&skl[e * OB_STR + col + 8];
        }
#pragma unroll
        for (int mi = 0; mi < 2; mi++)
#pragma unroll
            for (int ni = 0; ni < 2; ni++) {
                mmaf16(c[mi][ni], ah[mi], bh2[ni]);
                mmaf16(c[mi][ni], ah[mi], bl2[ni]);
            }
    }

    // ---- cooperative lepe: reuse sa/skh/skl region as fp32 plane [e][132] ----
    __syncthreads();
    float* slepe = (float*)sm_raw;
#pragma unroll
    for (int it = 0; it < 2; it++) {
        int u = it * 512 + tid;
        int e = u >> 4, seg = u & 15;
        int y = seg >> 2, x0 = (seg & 3) * 8;
        const float* wv = &sw[e * 9];
        float acc[8];
        float bs = sbias[e];
#pragma unroll
        for (int t = 0; t < 8; t++) acc[t] = bs;
#pragma unroll
        for (int i = 0; i < 3; i++) {
            const float* rw = &sx[e * 198 + (y + i) * 33 + x0];
            float r[10];
            r[0] = (x0 > 0) ? rw[-1] : 0.f;
#pragma unroll
            for (int t = 0; t < 8; t++) r[t + 1] = rw[t];
            r[9] = (x0 + 8 < 32) ? rw[8] : 0.f;
            float w0 = wv[i * 3 + 0], w1 = wv[i * 3 + 1], w2 = wv[i * 3 + 2];
#pragma unroll
            for (int t = 0; t < 8; t++)
                acc[t] += w0 * r[t] + w1 * r[t + 1] + w2 * r[t + 2];
        }
        float4* d = (float4*)&slepe[e * 132 + y * 32 + x0];
        d[0] = make_float4(acc[0], acc[1], acc[2], acc[3]);
        d[1] = make_float4(acc[4], acc[5], acc[6], acc[7]);
    }
    __syncthreads();

    // epilogue: z scale + lepe read + STG
    float* O = out + qbase;
#pragma unroll
    for (int ni = 0; ni < 2; ni++) {
        int e0 = wn * 16 + ni * 8 + tg * 2;
        int e1 = e0 + 1;
#pragma unroll
        for (int mi = 0; mi < 2; mi++) {
            int nr0 = wm * 32 + mi * 16 + g4;
            int nr1 = nr0 + 8;
            float z0 = 1.f / (s_z[nr0] + 1e-6f);
            float z1 = 1.f / (s_z[nr1] + 1e-6f);
            size_t i00 = (size_t)e0 * NPOS + n0 + nr0;
            size_t i01 = (size_t)e1 * NPOS + n0 + nr0;
            size_t i10 = (size_t)e0 * NPOS + n0 + nr1;
            size_t i11 = (size_t)e1 * NPOS + n0 + nr1;
            O[i00] = c[mi][ni][0] * z0 + slepe[e0 * 132 + nr0];
            O[i01] = c[mi][ni][1] * z0 + slepe[e1 * 132 + nr0];
            O[i10] = c[mi][ni][2] * z1 + slepe[e0 * 132 + nr1];
            O[i11] = c[mi][ni][3] * z1 + slepe[e1 * 132 + nr1];
        }
    }
}

// ---------------- launch ----------------
extern "C" void kernel_launch(void* const* d_in, const int* in_sizes, int n_in,
                              void* d_out, int out_size) {
    const float* x      = (const float*)d_in[0];
    const float* qk_w   = (const float*)d_in[1];
    const float* qk_b   = (const float*)d_in[2];
    const float* lepe_w = (const float*)d_in[3];
    const float* lepe_b = (const float*)d_in[4];
    float* out = (float*)d_out;

    cudaFuncSetAttribute(proj_kernel, cudaFuncAttributeMaxDynamicSharedMemorySize, PROJ_SMEM);
    cudaFuncSetAttribute(out_kernel, cudaFuncAttributeMaxDynamicSharedMemorySize, OSMEM_BYTES);

    // launches: prep(1) proj(2) kv(3) out(4) -> ncu capture slot = out
    prep_all_kernel<<<BATCHN * DIMC * NPOS / 8 / 256, 256>>>(x, qk_w);
    proj_kernel<<<dim3(8, 8, 2 * BATCHN), 256, PROJ_SMEM>>>(qk_b);
    kv_kernel<<<dim3(BATCHN * NH, 8), 256>>>();
    out_kernel<<<dim3(8, BATCHN * NH), 512, OSMEM_BYTES>>>(out, lepe_w, lepe_b);
}